// round 4
// baseline (speedup 1.0000x reference)
#include <cuda_runtime.h>
#include <cstdint>

// ---------------------------------------------------------------------------
// out = sigmoid(BN( U@M1 + V@M2 )), U = x[:,0,:], V = x[:,1,:]+x[:,2,:]
//   M1 = w2a@w2b + 0.5*w1a@w1b
//   M2 = 0.5*w1a@w2b + (0.5*w2a + 0.25*w1a)@w1b
// Single (65536 x 512) @ (512 x 768) GEMM + BN + sigmoid.
// ---------------------------------------------------------------------------

#define NROWS   65536
#define DIN     768     // x row stride (3*256)
#define KDIM    512
#define EDIM    768

// __device__ scratch (allocation-free rule)
__device__ __align__(16) float g_L[512 * 1536];   // [w2a;0.5w1a | 0.5w1a;0.5w2a+0.25w1a]
__device__ __align__(16) float g_M[KDIM * EDIM];  // combined weight matrix
__device__ __align__(16) float g_psum[256 * EDIM];
__device__ __align__(16) float g_psqs[256 * EDIM];
__device__ __align__(16) float g_scale[EDIM];
__device__ __align__(16) float g_shift[EDIM];

// ---- f32x2 packed-math helpers (sm_100+ PTX) ------------------------------
__device__ __forceinline__ void fma2(unsigned long long& d,
                                     unsigned long long a,
                                     unsigned long long b) {
    asm("fma.rn.f32x2 %0, %1, %2, %0;" : "+l"(d) : "l"(a), "l"(b));
}
__device__ __forceinline__ unsigned long long dup2(float x) {
    unsigned long long r;
    unsigned int u = __float_as_uint(x);
    asm("mov.b64 %0, {%1, %1};" : "=l"(r) : "r"(u));
    return r;
}
__device__ __forceinline__ float2 unpack2(unsigned long long v) {
    unsigned int lo, hi;
    asm("mov.b64 {%0, %1}, %2;" : "=r"(lo), "=r"(hi) : "l"(v));
    return make_float2(__uint_as_float(lo), __uint_as_float(hi));
}

// ---------------------------------------------------------------------------
// K0: build concatenated left matrix  g_L (512 x 1536)
//   cols [0,768):   multiplies w2b   -> rows<256: w2a, rows>=256: 0.5*w1a
//   cols [768,1536): multiplies w1b  -> rows<256: 0.5*w1a, rows>=256: 0.5*w2a+0.25*w1a
// ---------------------------------------------------------------------------
__global__ void build_L(const float* __restrict__ w1a, const float* __restrict__ w2a) {
    int idx = blockIdx.x * blockDim.x + threadIdx.x;
    if (idx >= 512 * 1536) return;
    int i = idx / 1536;
    int j = idx % 1536;
    float v;
    if (j < 768) {
        v = (i < 256) ? w2a[i * 768 + j] : 0.5f * w1a[(i - 256) * 768 + j];
    } else {
        int jj = j - 768;
        v = (i < 256) ? 0.5f * w1a[i * 768 + jj]
                      : 0.5f * w2a[(i - 256) * 768 + jj] + 0.25f * w1a[(i - 256) * 768 + jj];
    }
    g_L[idx] = v;
}

// ---------------------------------------------------------------------------
// K1: g_M (512 x 768) = g_L (512 x 1536) @ [w2b ; w1b] (1536 x 768)
// 64x64 tiles, 256 threads, 4x4 per thread, K-block 16.
// ---------------------------------------------------------------------------
__global__ void __launch_bounds__(256) gemm_weights(const float* __restrict__ w1b,
                                                    const float* __restrict__ w2b) {
    __shared__ __align__(16) float As[16][64];
    __shared__ __align__(16) float Bs[16][64];
    const int e0 = blockIdx.x * 64;
    const int i0 = blockIdx.y * 64;
    const int t  = threadIdx.x;
    const int tx = t & 15;   // N
    const int ty = t >> 4;   // M
    float acc[4][4] = {};

    for (int j0 = 0; j0 < 1536; j0 += 16) {
        {   // A tile: 64 rows x 16 k -> 256 threads x 1 float4
            int r  = t >> 2;
            int jq = (t & 3) * 4;
            float4 v = *(const float4*)&g_L[(i0 + r) * 1536 + j0 + jq];
            As[jq + 0][r] = v.x; As[jq + 1][r] = v.y;
            As[jq + 2][r] = v.z; As[jq + 3][r] = v.w;
        }
        {   // B tile: 16 k-rows x 64 cols
            int k  = t >> 4;
            int eq = (t & 15) * 4;
            int j  = j0 + k;
            const float* src = (j < 768) ? (w2b + (size_t)j * 768)
                                         : (w1b + (size_t)(j - 768) * 768);
            *(float4*)&Bs[k][eq] = *(const float4*)(src + e0 + eq);
        }
        __syncthreads();
        #pragma unroll
        for (int k = 0; k < 16; ++k) {
            float4 a = *(const float4*)&As[k][ty * 4];
            float4 b = *(const float4*)&Bs[k][tx * 4];
            float av[4] = {a.x, a.y, a.z, a.w};
            float bv[4] = {b.x, b.y, b.z, b.w};
            #pragma unroll
            for (int i = 0; i < 4; ++i)
                #pragma unroll
                for (int j = 0; j < 4; ++j)
                    acc[i][j] = fmaf(av[i], bv[j], acc[i][j]);
        }
        __syncthreads();
    }
    #pragma unroll
    for (int i = 0; i < 4; ++i) {
        float4 v = make_float4(acc[i][0], acc[i][1], acc[i][2], acc[i][3]);
        *(float4*)&g_M[(size_t)(i0 + ty * 4 + i) * EDIM + e0 + tx * 4] = v;
    }
}

// ---------------------------------------------------------------------------
// K2: main GEMM  OUT(65536 x 768) = A(65536 x 512) @ g_M(512 x 768)
//   A(n,k) = X[n*768+k] + (k>=256 ? X[n*768+k+256] : 0)   (built on the fly)
// 128x64 tiles, 256 threads, 8x4 per thread, f32x2 packed FMA (M-paired).
// ---------------------------------------------------------------------------
__global__ void __launch_bounds__(256) gemm_main(const float* __restrict__ X,
                                                 float* __restrict__ OUT) {
    __shared__ __align__(16) float As[16][128];
    __shared__ __align__(16) float Bs[16][64];
    const int e0 = blockIdx.x * 64;    // fast index -> col blocks share A tile in L2
    const int n0 = blockIdx.y * 128;
    const int t  = threadIdx.x;
    const int tx = t & 15;   // N: 4 cols
    const int ty = t >> 4;   // M: 8 rows = 4 pairs

    unsigned long long acc[4][4];      // [m-pair][n]  (lo=even row, hi=odd row)
    #pragma unroll
    for (int i = 0; i < 4; ++i)
        #pragma unroll
        for (int j = 0; j < 4; ++j) acc[i][j] = 0ULL;

    for (int k0 = 0; k0 < KDIM; k0 += 16) {
        // A tile: 128 rows x 16 k = 512 float4, 2 per thread
        #pragma unroll
        for (int i = 0; i < 2; ++i) {
            int idx4 = t * 2 + i;
            int row  = idx4 >> 2;
            int kq   = (idx4 & 3) * 4;
            int k    = k0 + kq;
            const float* p = X + (size_t)(n0 + row) * DIN + k;
            float4 v = *(const float4*)p;
            if (k >= 256) {
                float4 w = *(const float4*)(p + 256);
                v.x += w.x; v.y += w.y; v.z += w.z; v.w += w.w;
            }
            As[kq + 0][row] = v.x; As[kq + 1][row] = v.y;
            As[kq + 2][row] = v.z; As[kq + 3][row] = v.w;
        }
        {   // B tile: 16 k-rows x 64 cols
            int k  = t >> 4;
            int eq = (t & 15) * 4;
            *(float4*)&Bs[k][eq] =
                *(const float4*)(g_M + (size_t)(k0 + k) * EDIM + e0 + eq);
        }
        __syncthreads();
        #pragma unroll
        for (int k = 0; k < 16; ++k) {
            // 8 consecutive m-values as 4 packed f32x2 operands (free pairing)
            ulonglong2 A0 = *(const ulonglong2*)&As[k][ty * 8];
            ulonglong2 A1 = *(const ulonglong2*)&As[k][ty * 8 + 4];
            float4 b = *(const float4*)&Bs[k][tx * 4];
            unsigned long long b0 = dup2(b.x), b1 = dup2(b.y),
                               b2 = dup2(b.z), b3 = dup2(b.w);
            fma2(acc[0][0], A0.x, b0); fma2(acc[0][1], A0.x, b1);
            fma2(acc[0][2], A0.x, b2); fma2(acc[0][3], A0.x, b3);
            fma2(acc[1][0], A0.y, b0); fma2(acc[1][1], A0.y, b1);
            fma2(acc[1][2], A0.y, b2); fma2(acc[1][3], A0.y, b3);
            fma2(acc[2][0], A1.x, b0); fma2(acc[2][1], A1.x, b1);
            fma2(acc[2][2], A1.x, b2); fma2(acc[2][3], A1.x, b3);
            fma2(acc[3][0], A1.y, b0); fma2(acc[3][1], A1.y, b1);
            fma2(acc[3][2], A1.y, b2); fma2(acc[3][3], A1.y, b3);
        }
        __syncthreads();
    }
    #pragma unroll
    for (int mp = 0; mp < 4; ++mp) {
        float2 c0 = unpack2(acc[mp][0]);
        float2 c1 = unpack2(acc[mp][1]);
        float2 c2 = unpack2(acc[mp][2]);
        float2 c3 = unpack2(acc[mp][3]);
        size_t r0 = (size_t)(n0 + ty * 8 + mp * 2) * EDIM + e0 + tx * 4;
        *(float4*)(OUT + r0)        = make_float4(c0.x, c1.x, c2.x, c3.x);
        *(float4*)(OUT + r0 + EDIM) = make_float4(c0.y, c1.y, c2.y, c3.y);
    }
}

// ---------------------------------------------------------------------------
// K3: per-column partial sums / sums-of-squares (deterministic reduction)
// 256 blocks x 256 rows each; thread t owns cols {t, t+256, t+512}.
// ---------------------------------------------------------------------------
__global__ void __launch_bounds__(256) bn_partial(const float* __restrict__ OUT) {
    const int b = blockIdx.x;
    const int t = threadIdx.x;
    float s0 = 0.f, s1 = 0.f, s2 = 0.f, q0 = 0.f, q1 = 0.f, q2 = 0.f;
    const float* base = OUT + (size_t)b * 256 * EDIM;
    for (int r = 0; r < 256; ++r) {
        const float* row = base + (size_t)r * EDIM;
        float v0 = row[t];
        float v1 = row[t + 256];
        float v2 = row[t + 512];
        s0 += v0; q0 = fmaf(v0, v0, q0);
        s1 += v1; q1 = fmaf(v1, v1, q1);
        s2 += v2; q2 = fmaf(v2, v2, q2);
    }
    g_psum[b * EDIM + t]       = s0;  g_psqs[b * EDIM + t]       = q0;
    g_psum[b * EDIM + t + 256] = s1;  g_psqs[b * EDIM + t + 256] = q1;
    g_psum[b * EDIM + t + 512] = s2;  g_psqs[b * EDIM + t + 512] = q2;
}

// ---------------------------------------------------------------------------
// K4: finalize stats -> per-column scale/shift
// ---------------------------------------------------------------------------
__global__ void bn_finalize(const float* __restrict__ gamma,
                            const float* __restrict__ beta) {
    int c = blockIdx.x * blockDim.x + threadIdx.x;
    if (c >= EDIM) return;
    float s = 0.f, q = 0.f;
    for (int b = 0; b < 256; ++b) {
        s += g_psum[b * EDIM + c];
        q += g_psqs[b * EDIM + c];
    }
    const float inv_n = 1.f / (float)NROWS;
    float mean = s * inv_n;
    float var  = q * inv_n - mean * mean;
    float rstd = rsqrtf(var + 1e-5f);
    float g = gamma[c] * rstd;
    g_scale[c] = g;
    g_shift[c] = beta[c] - mean * g;
}

// ---------------------------------------------------------------------------
// K5: in-place normalize + sigmoid.  One row per block, 192 threads x float4.
// ---------------------------------------------------------------------------
__global__ void __launch_bounds__(192) bn_sigmoid(float* __restrict__ OUT) {
    const int row = blockIdx.x;
    const int t   = threadIdx.x;                       // 0..191 -> cols t*4..t*4+3
    float4* p = (float4*)(OUT + (size_t)row * EDIM) + t;
    float4 v  = *p;
    float4 sc = ((const float4*)g_scale)[t];
    float4 sh = ((const float4*)g_shift)[t];
    v.x = 1.f / (1.f + expf(-(fmaf(v.x, sc.x, sh.x))));
    v.y = 1.f / (1.f + expf(-(fmaf(v.y, sc.y, sh.y))));
    v.z = 1.f / (1.f + expf(-(fmaf(v.z, sc.z, sh.z))));
    v.w = 1.f / (1.f + expf(-(fmaf(v.w, sc.w, sh.w))));
    *p = v;
}

// ---------------------------------------------------------------------------
extern "C" void kernel_launch(void* const* d_in, const int* in_sizes, int n_in,
                              void* d_out, int out_size) {
    const float* x     = (const float*)d_in[0];   // (65536, 3, 256)
    const float* w1a   = (const float*)d_in[1];   // (256, 768)
    const float* w2a   = (const float*)d_in[2];   // (256, 768)
    const float* w1b   = (const float*)d_in[3];   // (768, 768)
    const float* w2b   = (const float*)d_in[4];   // (768, 768)
    const float* gamma = (const float*)d_in[5];   // (768,)
    const float* beta  = (const float*)d_in[6];   // (768,)
    float* out = (float*)d_out;                   // (65536, 768)

    build_L<<<768, 1024>>>(w1a, w2a);
    gemm_weights<<<dim3(EDIM / 64, 512 / 64), 256>>>(w1b, w2b);
    gemm_main<<<dim3(EDIM / 64, NROWS / 128), 256>>>(x, out);
    bn_partial<<<256, 256>>>(out);
    bn_finalize<<<3, 256>>>(gamma, beta);
    bn_sigmoid<<<NROWS, 192>>>(out);
}

// round 6
// speedup vs baseline: 1.9494x; 1.9494x over previous
#include <cuda_runtime.h>
#include <cuda_bf16.h>
#include <cstdint>

// ---------------------------------------------------------------------------
// out = sigmoid(BN( A @ M )),  A (65536 x 512) built from x, M (512 x 768)
// pre-combined from the 4 weight matrices.
// Main GEMM: mma.sync m16n8k16 bf16 (baseline PTX — tcgen05 is blocked by the
// harness's .target sm_103), fp32 accum, 3-term hi/lo split for fp32 accuracy.
// CTA 128x128, 8 warps (2x4), warp 64x32, K-block 32, 3-stage cp.async pipe.
// ---------------------------------------------------------------------------

#define NROWS   65536
#define DIN     768
#define KDIM    512
#define EDIM    768

#define KB      32          // K per stage
#define NITER   (KDIM / KB) // 16

// smem stage: Ah[128x32] Al Bh[128x32] Bl, 80B row stride (64B data + 16B pad)
#define ROWB    80
#define TERMB   (128 * ROWB)        // 10240
#define STG     (4 * TERMB)         // 40960
#define SMEMB   (3 * STG)           // 122880

// __device__ scratch (allocation-free rule)
__device__ __align__(16) float          g_L[512 * 1536];
__device__ __align__(16) float          g_M[KDIM * EDIM];
__device__ __align__(16) __nv_bfloat16  g_Bh[EDIM * KDIM];       // [e][k]
__device__ __align__(16) __nv_bfloat16  g_Bl[EDIM * KDIM];
__device__ __align__(16) __nv_bfloat16  g_Ah[(size_t)NROWS * KDIM]; // [n][k]
__device__ __align__(16) __nv_bfloat16  g_Al[(size_t)NROWS * KDIM];
__device__ __align__(16) float          g_psum[256 * EDIM];
__device__ __align__(16) float          g_psqs[256 * EDIM];
__device__ __align__(16) float          g_scale[EDIM];
__device__ __align__(16) float          g_shift[EDIM];

// ---------------- PTX helpers (all baseline sm_80+ features) ----------------
__device__ __forceinline__ uint32_t smem_u32(const void* p) {
    uint32_t a;
    asm("{ .reg .u64 t; cvta.to.shared.u64 t, %1; cvt.u32.u64 %0, t; }" : "=r"(a) : "l"(p));
    return a;
}
__device__ __forceinline__ void cp16(uint32_t dst, const void* src) {
    asm volatile("cp.async.cg.shared.global [%0], [%1], 16;" :: "r"(dst), "l"(src) : "memory");
}
__device__ __forceinline__ void ldsm4(uint32_t* r, uint32_t a) {
    asm volatile("ldmatrix.sync.aligned.m8n8.x4.shared.b16 {%0,%1,%2,%3}, [%4];"
                 : "=r"(r[0]), "=r"(r[1]), "=r"(r[2]), "=r"(r[3]) : "r"(a));
}
__device__ __forceinline__ void mma_bf16(float* c, const uint32_t* a,
                                         uint32_t b0, uint32_t b1) {
    asm volatile(
        "mma.sync.aligned.m16n8k16.row.col.f32.bf16.bf16.f32 "
        "{%0,%1,%2,%3}, {%4,%5,%6,%7}, {%8,%9}, {%0,%1,%2,%3};"
        : "+f"(c[0]), "+f"(c[1]), "+f"(c[2]), "+f"(c[3])
        : "r"(a[0]), "r"(a[1]), "r"(a[2]), "r"(a[3]), "r"(b0), "r"(b1));
}

// ---------------------------------------------------------------------------
// K0: build concatenated left matrix g_L (512 x 1536)   [proven]
// ---------------------------------------------------------------------------
__global__ void build_L(const float* __restrict__ w1a, const float* __restrict__ w2a) {
    int idx = blockIdx.x * blockDim.x + threadIdx.x;
    if (idx >= 512 * 1536) return;
    int i = idx / 1536;
    int j = idx % 1536;
    float v;
    if (j < 768) {
        v = (i < 256) ? w2a[i * 768 + j] : 0.5f * w1a[(i - 256) * 768 + j];
    } else {
        int jj = j - 768;
        v = (i < 256) ? 0.5f * w1a[i * 768 + jj]
                      : 0.5f * w2a[(i - 256) * 768 + jj] + 0.25f * w1a[(i - 256) * 768 + jj];
    }
    g_L[idx] = v;
}

// ---------------------------------------------------------------------------
// K1: g_M = g_L @ [w2b ; w1b]   fp32 exact   [proven]
// ---------------------------------------------------------------------------
__global__ void __launch_bounds__(256) gemm_weights(const float* __restrict__ w1b,
                                                    const float* __restrict__ w2b) {
    __shared__ __align__(16) float As[16][64];
    __shared__ __align__(16) float Bs[16][64];
    const int e0 = blockIdx.x * 64;
    const int i0 = blockIdx.y * 64;
    const int t  = threadIdx.x;
    const int tx = t & 15;
    const int ty = t >> 4;
    float acc[4][4] = {};

    for (int j0 = 0; j0 < 1536; j0 += 16) {
        {
            int r  = t >> 2;
            int jq = (t & 3) * 4;
            float4 v = *(const float4*)&g_L[(i0 + r) * 1536 + j0 + jq];
            As[jq + 0][r] = v.x; As[jq + 1][r] = v.y;
            As[jq + 2][r] = v.z; As[jq + 3][r] = v.w;
        }
        {
            int k  = t >> 4;
            int eq = (t & 15) * 4;
            int j  = j0 + k;
            const float* src = (j < 768) ? (w2b + (size_t)j * 768)
                                         : (w1b + (size_t)(j - 768) * 768);
            *(float4*)&Bs[k][eq] = *(const float4*)(src + e0 + eq);
        }
        __syncthreads();
        #pragma unroll
        for (int k = 0; k < 16; ++k) {
            float4 a = *(const float4*)&As[k][ty * 4];
            float4 b = *(const float4*)&Bs[k][tx * 4];
            float av[4] = {a.x, a.y, a.z, a.w};
            float bv[4] = {b.x, b.y, b.z, b.w};
            #pragma unroll
            for (int i = 0; i < 4; ++i)
                #pragma unroll
                for (int j = 0; j < 4; ++j)
                    acc[i][j] = fmaf(av[i], bv[j], acc[i][j]);
        }
        __syncthreads();
    }
    #pragma unroll
    for (int i = 0; i < 4; ++i)
        *(float4*)&g_M[(size_t)(i0 + ty * 4 + i) * EDIM + e0 + tx * 4] =
            make_float4(acc[i][0], acc[i][1], acc[i][2], acc[i][3]);
}

// ---------------------------------------------------------------------------
// K2: g_M -> g_Bh/g_Bl (bf16 hi/lo, [e][k] K-major)
// ---------------------------------------------------------------------------
__global__ void __launch_bounds__(256) conv_B() {
    int idx = blockIdx.x * 256 + threadIdx.x;       // 512*768
    int e = idx % EDIM;
    int k = idx / EDIM;
    float v = g_M[(size_t)k * EDIM + e];
    __nv_bfloat16 h = __float2bfloat16(v);
    g_Bh[(size_t)e * KDIM + k] = h;
    g_Bl[(size_t)e * KDIM + k] = __float2bfloat16(v - __bfloat162float(h));
}

// ---------------------------------------------------------------------------
// K3: x -> g_Ah/g_Al.  A(n,k) = x[n,0,k] (k<256) / x[n,1,..]+x[n,2,..]
// ---------------------------------------------------------------------------
__global__ void __launch_bounds__(256) conv_A(const float* __restrict__ X) {
    int id = blockIdx.x * 256 + threadIdx.x;        // NROWS*64
    int n  = id >> 6;
    int k  = (id & 63) * 8;
    const float* p = X + (size_t)n * DIN + k;
    float4 v0 = *(const float4*)p;
    float4 v1 = *(const float4*)(p + 4);
    if (k >= 256) {
        float4 w0 = *(const float4*)(p + 256);
        float4 w1 = *(const float4*)(p + 260);
        v0.x += w0.x; v0.y += w0.y; v0.z += w0.z; v0.w += w0.w;
        v1.x += w1.x; v1.y += w1.y; v1.z += w1.z; v1.w += w1.w;
    }
    float a[8] = {v0.x, v0.y, v0.z, v0.w, v1.x, v1.y, v1.z, v1.w};
    uint32_t hw[4], lw[4];
    #pragma unroll
    for (int j = 0; j < 4; ++j) {
        __nv_bfloat16 h0 = __float2bfloat16(a[2*j]);
        __nv_bfloat16 h1 = __float2bfloat16(a[2*j+1]);
        __nv_bfloat16 l0 = __float2bfloat16(a[2*j]   - __bfloat162float(h0));
        __nv_bfloat16 l1 = __float2bfloat16(a[2*j+1] - __bfloat162float(h1));
        hw[j] = (uint32_t)__bfloat16_as_ushort(h0) | ((uint32_t)__bfloat16_as_ushort(h1) << 16);
        lw[j] = (uint32_t)__bfloat16_as_ushort(l0) | ((uint32_t)__bfloat16_as_ushort(l1) << 16);
    }
    size_t o = (size_t)n * KDIM + k;
    *(uint4*)(g_Ah + o) = make_uint4(hw[0], hw[1], hw[2], hw[3]);
    *(uint4*)(g_Al + o) = make_uint4(lw[0], lw[1], lw[2], lw[3]);
}

// ---------------------------------------------------------------------------
// K4: main GEMM via mma.sync bf16.  grid (6, 512), 256 threads.
// ---------------------------------------------------------------------------
__device__ __forceinline__ void stage_issue(uint32_t st, int t, int n0, int e0, int k0) {
    #pragma unroll
    for (int j = 0; j < 8; ++j) {
        int idx  = t + 256 * j;          // 0..2047
        int part = idx >> 10;            // 0: A, 1: B
        int term = (idx >> 9) & 1;       // 0: hi, 1: lo
        int rr   = (idx >> 2) & 127;
        int c    = idx & 3;
        uint32_t dst = st + (uint32_t)(part * 2 * TERMB + term * TERMB + rr * ROWB + c * 16);
        const __nv_bfloat16* g = part ? (term ? g_Bl : g_Bh) : (term ? g_Al : g_Ah);
        int base = part ? e0 : n0;
        cp16(dst, g + (size_t)(base + rr) * KDIM + k0 + c * 8);
    }
    asm volatile("cp.async.commit_group;" ::: "memory");
}

__global__ void __launch_bounds__(256, 1) gemm_mma(float* __restrict__ OUT) {
    extern __shared__ char smem[];
    const uint32_t sb = smem_u32(smem);
    const int t  = threadIdx.x;
    const int w  = t >> 5;
    const int l  = t & 31;
    const int mw = w & 1;                // M-warp (64 rows each)
    const int nw = w >> 1;               // N-warp (32 cols each)
    const int e0 = blockIdx.x * 128;
    const int n0 = blockIdx.y * 128;

    float acc[4][4][4];
    #pragma unroll
    for (int a = 0; a < 4; ++a)
        #pragma unroll
        for (int b = 0; b < 4; ++b)
            #pragma unroll
            for (int c = 0; c < 4; ++c) acc[a][b][c] = 0.f;

    // ldmatrix lane addresses (80B stride -> conflict-free, 5 coprime 8)
    const uint32_t a_lane = (uint32_t)((mw * 64 + (l & 15)) * ROWB + (l >> 4) * 16);
    const uint32_t b_lane = (uint32_t)((nw * 32 + ((l >> 4) & 1) * 8 + (l & 7)) * ROWB
                                       + ((l >> 3) & 1) * 16);

    stage_issue(sb + 0 * STG, t, n0, e0, 0);
    stage_issue(sb + 1 * STG, t, n0, e0, KB);

    int s = 0;
    #pragma unroll 1
    for (int i = 0; i < NITER; ++i) {
        if (i != NITER - 1) asm volatile("cp.async.wait_group 1;" ::: "memory");
        else                asm volatile("cp.async.wait_group 0;" ::: "memory");
        __syncthreads();

        const uint32_t st = sb + (uint32_t)s * STG;
        #pragma unroll
        for (int kk = 0; kk < 2; ++kk) {
            uint32_t Ahf[4][4], Alf[4][4], Bhf[2][4], Blf[2][4];
            #pragma unroll
            for (int mt = 0; mt < 4; ++mt) {
                ldsm4(Ahf[mt], st + a_lane + mt * (16 * ROWB) + kk * 32);
                ldsm4(Alf[mt], st + TERMB + a_lane + mt * (16 * ROWB) + kk * 32);
            }
            #pragma unroll
            for (int p = 0; p < 2; ++p) {
                ldsm4(Bhf[p], st + 2 * TERMB + b_lane + p * (16 * ROWB) + kk * 32);
                ldsm4(Blf[p], st + 3 * TERMB + b_lane + p * (16 * ROWB) + kk * 32);
            }
            #pragma unroll
            for (int mt = 0; mt < 4; ++mt)
                #pragma unroll
                for (int nt = 0; nt < 4; ++nt) {
                    int p = nt >> 1, h = (nt & 1) * 2;
                    mma_bf16(acc[mt][nt], Ahf[mt], Bhf[p][h], Bhf[p][h + 1]);
                    mma_bf16(acc[mt][nt], Ahf[mt], Blf[p][h], Blf[p][h + 1]);
                    mma_bf16(acc[mt][nt], Alf[mt], Bhf[p][h], Bhf[p][h + 1]);
                }
        }

        if (i + 2 < NITER) {
            int s2 = s + 2; if (s2 >= 3) s2 -= 3;
            stage_issue(sb + (uint32_t)s2 * STG, t, n0, e0, (i + 2) * KB);
        }
        if (++s == 3) s = 0;
    }

    // epilogue: mma C layout -> OUT
    const int r0 = n0 + mw * 64;
    const int c0 = e0 + nw * 32;
    const int lr = l >> 2;
    const int lc = (l & 3) * 2;
    #pragma unroll
    for (int mt = 0; mt < 4; ++mt)
        #pragma unroll
        for (int nt = 0; nt < 4; ++nt) {
            size_t o = (size_t)(r0 + mt * 16 + lr) * EDIM + c0 + nt * 8 + lc;
            *(float2*)(OUT + o)            = make_float2(acc[mt][nt][0], acc[mt][nt][1]);
            *(float2*)(OUT + o + 8 * EDIM) = make_float2(acc[mt][nt][2], acc[mt][nt][3]);
        }
}

// ---------------------------------------------------------------------------
// BN chain   [proven]
// ---------------------------------------------------------------------------
__global__ void __launch_bounds__(256) bn_partial(const float* __restrict__ OUT) {
    const int b = blockIdx.x;
    const int t = threadIdx.x;
    float s0 = 0.f, s1 = 0.f, s2 = 0.f, q0 = 0.f, q1 = 0.f, q2 = 0.f;
    const float* base = OUT + (size_t)b * 256 * EDIM;
    for (int r = 0; r < 256; ++r) {
        const float* row = base + (size_t)r * EDIM;
        float v0 = row[t];
        float v1 = row[t + 256];
        float v2 = row[t + 512];
        s0 += v0; q0 = fmaf(v0, v0, q0);
        s1 += v1; q1 = fmaf(v1, v1, q1);
        s2 += v2; q2 = fmaf(v2, v2, q2);
    }
    g_psum[b * EDIM + t]       = s0;  g_psqs[b * EDIM + t]       = q0;
    g_psum[b * EDIM + t + 256] = s1;  g_psqs[b * EDIM + t + 256] = q1;
    g_psum[b * EDIM + t + 512] = s2;  g_psqs[b * EDIM + t + 512] = q2;
}

__global__ void bn_finalize(const float* __restrict__ gamma,
                            const float* __restrict__ beta) {
    int c = blockIdx.x * blockDim.x + threadIdx.x;
    if (c >= EDIM) return;
    float s = 0.f, q = 0.f;
    for (int b = 0; b < 256; ++b) {
        s += g_psum[b * EDIM + c];
        q += g_psqs[b * EDIM + c];
    }
    const float inv_n = 1.f / (float)NROWS;
    float mean = s * inv_n;
    float var  = q * inv_n - mean * mean;
    float rstd = rsqrtf(var + 1e-5f);
    float g = gamma[c] * rstd;
    g_scale[c] = g;
    g_shift[c] = beta[c] - mean * g;
}

__global__ void __launch_bounds__(192) bn_sigmoid(float* __restrict__ OUT) {
    const int row = blockIdx.x;
    const int t   = threadIdx.x;
    float4* p = (float4*)(OUT + (size_t)row * EDIM) + t;
    float4 v  = *p;
    float4 sc = ((const float4*)g_scale)[t];
    float4 sh = ((const float4*)g_shift)[t];
    v.x = 1.f / (1.f + expf(-(fmaf(v.x, sc.x, sh.x))));
    v.y = 1.f / (1.f + expf(-(fmaf(v.y, sc.y, sh.y))));
    v.z = 1.f / (1.f + expf(-(fmaf(v.z, sc.z, sh.z))));
    v.w = 1.f / (1.f + expf(-(fmaf(v.w, sc.w, sh.w))));
    *p = v;
}

// ---------------------------------------------------------------------------
extern "C" void kernel_launch(void* const* d_in, const int* in_sizes, int n_in,
                              void* d_out, int out_size) {
    const float* x     = (const float*)d_in[0];
    const float* w1a   = (const float*)d_in[1];
    const float* w2a   = (const float*)d_in[2];
    const float* w1b   = (const float*)d_in[3];
    const float* w2b   = (const float*)d_in[4];
    const float* gamma = (const float*)d_in[5];
    const float* beta  = (const float*)d_in[6];
    float* out = (float*)d_out;

    cudaFuncSetAttribute(gemm_mma, cudaFuncAttributeMaxDynamicSharedMemorySize, SMEMB);

    build_L<<<768, 1024>>>(w1a, w2a);
    gemm_weights<<<dim3(EDIM / 64, 512 / 64), 256>>>(w1b, w2b);
    conv_B<<<(KDIM * EDIM) / 256, 256>>>();
    conv_A<<<NROWS / 4, 256>>>(x);
    gemm_mma<<<dim3(EDIM / 128, NROWS / 128), 256, SMEMB>>>(out);
    bn_partial<<<256, 256>>>(out);
    bn_finalize<<<3, 256>>>(gamma, beta);
    bn_sigmoid<<<NROWS, 192>>>(out);
}

// round 7
// speedup vs baseline: 2.2966x; 1.1781x over previous
#include <cuda_runtime.h>
#include <cuda_bf16.h>
#include <cuda_fp16.h>
#include <cstdint>

// ---------------------------------------------------------------------------
// out = sigmoid(BN( A @ M )),  A (65536 x 512) built from x, M (512 x 768)
// pre-combined from the 4 weight matrices.
// Main GEMM: single-term fp16 mma.sync m16n8k16 (legacy HMMA floor is
// ~512 MAC/cyc/SM on sm_103; tcgen05 is blocked by the harness's .target).
// fp16 per-product error 2^-11 -> final rel_err ~2.5e-4 (<< 1e-3 gate).
// CTA 128x128, 8 warps (2x4), warp 64x32, K-block 32, 3-stage cp.async pipe.
// ---------------------------------------------------------------------------

#define NROWS   65536
#define DIN     768
#define KDIM    512
#define EDIM    768

#define KB      32          // K per stage
#define NITER   (KDIM / KB) // 16

// smem stage: Af[128x32] Bf[128x32] fp16, 80B row stride (64B data + 16B pad)
#define ROWB    80
#define TERMB   (128 * ROWB)        // 10240
#define STG     (2 * TERMB)         // 20480
#define SMEMB   (3 * STG)           // 61440

// __device__ scratch (allocation-free rule)
__device__ __align__(16) float   g_L[512 * 1536];
__device__ __align__(16) float   g_M[KDIM * EDIM];
__device__ __align__(16) __half  g_Bf[EDIM * KDIM];          // [e][k]
__device__ __align__(16) __half  g_Af[(size_t)NROWS * KDIM]; // [n][k]
__device__ __align__(16) float   g_psum[512 * EDIM];
__device__ __align__(16) float   g_psqs[512 * EDIM];
__device__ __align__(16) float   g_scale[EDIM];
__device__ __align__(16) float   g_shift[EDIM];

// ---------------- PTX helpers (baseline sm_80+ features only) ---------------
__device__ __forceinline__ uint32_t smem_u32(const void* p) {
    uint32_t a;
    asm("{ .reg .u64 t; cvta.to.shared.u64 t, %1; cvt.u32.u64 %0, t; }" : "=r"(a) : "l"(p));
    return a;
}
__device__ __forceinline__ void cp16(uint32_t dst, const void* src) {
    asm volatile("cp.async.cg.shared.global [%0], [%1], 16;" :: "r"(dst), "l"(src) : "memory");
}
__device__ __forceinline__ void ldsm4(uint32_t* r, uint32_t a) {
    asm volatile("ldmatrix.sync.aligned.m8n8.x4.shared.b16 {%0,%1,%2,%3}, [%4];"
                 : "=r"(r[0]), "=r"(r[1]), "=r"(r[2]), "=r"(r[3]) : "r"(a));
}
__device__ __forceinline__ void mma_f16(float* c, const uint32_t* a,
                                        uint32_t b0, uint32_t b1) {
    asm volatile(
        "mma.sync.aligned.m16n8k16.row.col.f32.f16.f16.f32 "
        "{%0,%1,%2,%3}, {%4,%5,%6,%7}, {%8,%9}, {%0,%1,%2,%3};"
        : "+f"(c[0]), "+f"(c[1]), "+f"(c[2]), "+f"(c[3])
        : "r"(a[0]), "r"(a[1]), "r"(a[2]), "r"(a[3]), "r"(b0), "r"(b1));
}

// ---------------------------------------------------------------------------
// K0: build concatenated left matrix g_L (512 x 1536)   [proven]
// ---------------------------------------------------------------------------
__global__ void build_L(const float* __restrict__ w1a, const float* __restrict__ w2a) {
    int idx = blockIdx.x * blockDim.x + threadIdx.x;
    if (idx >= 512 * 1536) return;
    int i = idx / 1536;
    int j = idx % 1536;
    float v;
    if (j < 768) {
        v = (i < 256) ? w2a[i * 768 + j] : 0.5f * w1a[(i - 256) * 768 + j];
    } else {
        int jj = j - 768;
        v = (i < 256) ? 0.5f * w1a[i * 768 + jj]
                      : 0.5f * w2a[(i - 256) * 768 + jj] + 0.25f * w1a[(i - 256) * 768 + jj];
    }
    g_L[idx] = v;
}

// ---------------------------------------------------------------------------
// K1: g_M = g_L @ [w2b ; w1b]   fp32 exact   [proven]
// ---------------------------------------------------------------------------
__global__ void __launch_bounds__(256) gemm_weights(const float* __restrict__ w1b,
                                                    const float* __restrict__ w2b) {
    __shared__ __align__(16) float As[16][64];
    __shared__ __align__(16) float Bs[16][64];
    const int e0 = blockIdx.x * 64;
    const int i0 = blockIdx.y * 64;
    const int t  = threadIdx.x;
    const int tx = t & 15;
    const int ty = t >> 4;
    float acc[4][4] = {};

    for (int j0 = 0; j0 < 1536; j0 += 16) {
        {
            int r  = t >> 2;
            int jq = (t & 3) * 4;
            float4 v = *(const float4*)&g_L[(i0 + r) * 1536 + j0 + jq];
            As[jq + 0][r] = v.x; As[jq + 1][r] = v.y;
            As[jq + 2][r] = v.z; As[jq + 3][r] = v.w;
        }
        {
            int k  = t >> 4;
            int eq = (t & 15) * 4;
            int j  = j0 + k;
            const float* src = (j < 768) ? (w2b + (size_t)j * 768)
                                         : (w1b + (size_t)(j - 768) * 768);
            *(float4*)&Bs[k][eq] = *(const float4*)(src + e0 + eq);
        }
        __syncthreads();
        #pragma unroll
        for (int k = 0; k < 16; ++k) {
            float4 a = *(const float4*)&As[k][ty * 4];
            float4 b = *(const float4*)&Bs[k][tx * 4];
            float av[4] = {a.x, a.y, a.z, a.w};
            float bv[4] = {b.x, b.y, b.z, b.w};
            #pragma unroll
            for (int i = 0; i < 4; ++i)
                #pragma unroll
                for (int j = 0; j < 4; ++j)
                    acc[i][j] = fmaf(av[i], bv[j], acc[i][j]);
        }
        __syncthreads();
    }
    #pragma unroll
    for (int i = 0; i < 4; ++i)
        *(float4*)&g_M[(size_t)(i0 + ty * 4 + i) * EDIM + e0 + tx * 4] =
            make_float4(acc[i][0], acc[i][1], acc[i][2], acc[i][3]);
}

// ---------------------------------------------------------------------------
// K2: g_M -> g_Bf (fp16, [e][k] K-major transpose)
// ---------------------------------------------------------------------------
__global__ void __launch_bounds__(256) conv_B() {
    int idx = blockIdx.x * 256 + threadIdx.x;       // 512*768
    int e = idx % EDIM;
    int k = idx / EDIM;
    g_Bf[(size_t)e * KDIM + k] = __float2half_rn(g_M[(size_t)k * EDIM + e]);
}

// ---------------------------------------------------------------------------
// K3: x -> g_Af (fp16).  A(n,k) = x[n,0,k] (k<256) / x[n,1,..]+x[n,2,..]
// ---------------------------------------------------------------------------
__global__ void __launch_bounds__(256) conv_A(const float* __restrict__ X) {
    int id = blockIdx.x * 256 + threadIdx.x;        // NROWS*64 threads
    int n  = id >> 6;
    int k  = (id & 63) * 8;
    const float* p = X + (size_t)n * DIN + k;
    float4 v0 = *(const float4*)p;
    float4 v1 = *(const float4*)(p + 4);
    if (k >= 256) {
        float4 w0 = *(const float4*)(p + 256);
        float4 w1 = *(const float4*)(p + 260);
        v0.x += w0.x; v0.y += w0.y; v0.z += w0.z; v0.w += w0.w;
        v1.x += w1.x; v1.y += w1.y; v1.z += w1.z; v1.w += w1.w;
    }
    __half2 h0 = __float22half2_rn(make_float2(v0.x, v0.y));
    __half2 h1 = __float22half2_rn(make_float2(v0.z, v0.w));
    __half2 h2 = __float22half2_rn(make_float2(v1.x, v1.y));
    __half2 h3 = __float22half2_rn(make_float2(v1.z, v1.w));
    uint4 o;
    o.x = *(uint32_t*)&h0; o.y = *(uint32_t*)&h1;
    o.z = *(uint32_t*)&h2; o.w = *(uint32_t*)&h3;
    *(uint4*)(g_Af + (size_t)n * KDIM + k) = o;
}

// ---------------------------------------------------------------------------
// K4: main GEMM via fp16 mma.sync.  grid (6, 512), 256 threads.
// ---------------------------------------------------------------------------
__device__ __forceinline__ void stage_issue(uint32_t st, int t, int n0, int e0, int k0) {
    #pragma unroll
    for (int j = 0; j < 4; ++j) {
        int idx  = t + 256 * j;          // 0..1023
        int part = idx >> 9;             // 0: A, 1: B
        int rr   = (idx >> 2) & 127;
        int c    = idx & 3;
        uint32_t dst = st + (uint32_t)(part * TERMB + rr * ROWB + c * 16);
        const __half* g = part ? g_Bf : g_Af;
        int base = part ? e0 : n0;
        cp16(dst, g + (size_t)(base + rr) * KDIM + k0 + c * 8);
    }
    asm volatile("cp.async.commit_group;" ::: "memory");
}

__global__ void __launch_bounds__(256, 2) gemm_mma(float* __restrict__ OUT) {
    extern __shared__ char smem[];
    const uint32_t sb = smem_u32(smem);
    const int t  = threadIdx.x;
    const int w  = t >> 5;
    const int l  = t & 31;
    const int mw = w & 1;                // M-warp (64 rows each)
    const int nw = w >> 1;               // N-warp (32 cols each)
    const int e0 = blockIdx.x * 128;
    const int n0 = blockIdx.y * 128;

    float acc[4][4][4];
    #pragma unroll
    for (int a = 0; a < 4; ++a)
        #pragma unroll
        for (int b = 0; b < 4; ++b)
            #pragma unroll
            for (int c = 0; c < 4; ++c) acc[a][b][c] = 0.f;

    // ldmatrix lane addresses (80B stride -> conflict-free, 5 coprime 8)
    const uint32_t a_lane = (uint32_t)((mw * 64 + (l & 15)) * ROWB + (l >> 4) * 16);
    const uint32_t b_lane = (uint32_t)((nw * 32 + ((l >> 4) & 1) * 8 + (l & 7)) * ROWB
                                       + ((l >> 3) & 1) * 16);

    stage_issue(sb + 0 * STG, t, n0, e0, 0);
    stage_issue(sb + 1 * STG, t, n0, e0, KB);

    int s = 0;
    #pragma unroll 1
    for (int i = 0; i < NITER; ++i) {
        if (i != NITER - 1) asm volatile("cp.async.wait_group 1;" ::: "memory");
        else                asm volatile("cp.async.wait_group 0;" ::: "memory");
        __syncthreads();

        const uint32_t st = sb + (uint32_t)s * STG;
        #pragma unroll
        for (int kk = 0; kk < 2; ++kk) {
            uint32_t Af[4][4], Bf[2][4];
            #pragma unroll
            for (int mt = 0; mt < 4; ++mt)
                ldsm4(Af[mt], st + a_lane + mt * (16 * ROWB) + kk * 32);
            #pragma unroll
            for (int p = 0; p < 2; ++p)
                ldsm4(Bf[p], st + TERMB + b_lane + p * (16 * ROWB) + kk * 32);
            #pragma unroll
            for (int mt = 0; mt < 4; ++mt)
                #pragma unroll
                for (int nt = 0; nt < 4; ++nt) {
                    int p = nt >> 1, h = (nt & 1) * 2;
                    mma_f16(acc[mt][nt], Af[mt], Bf[p][h], Bf[p][h + 1]);
                }
        }

        if (i + 2 < NITER) {
            int s2 = s + 2; if (s2 >= 3) s2 -= 3;
            stage_issue(sb + (uint32_t)s2 * STG, t, n0, e0, (i + 2) * KB);
        }
        if (++s == 3) s = 0;
    }

    // epilogue: mma C layout -> OUT
    const int r0 = n0 + mw * 64;
    const int c0 = e0 + nw * 32;
    const int lr = l >> 2;
    const int lc = (l & 3) * 2;
    #pragma unroll
    for (int mt = 0; mt < 4; ++mt)
        #pragma unroll
        for (int nt = 0; nt < 4; ++nt) {
            size_t o = (size_t)(r0 + mt * 16 + lr) * EDIM + c0 + nt * 8 + lc;
            *(float2*)(OUT + o)            = make_float2(acc[mt][nt][0], acc[mt][nt][1]);
            *(float2*)(OUT + o + 8 * EDIM) = make_float2(acc[mt][nt][2], acc[mt][nt][3]);
        }
}

// ---------------------------------------------------------------------------
// BN chain (bn_partial re-gridded to 512 blocks for occupancy)
// ---------------------------------------------------------------------------
__global__ void __launch_bounds__(256) bn_partial(const float* __restrict__ OUT) {
    const int b = blockIdx.x;
    const int t = threadIdx.x;
    float s0 = 0.f, s1 = 0.f, s2 = 0.f, q0 = 0.f, q1 = 0.f, q2 = 0.f;
    const float* base = OUT + (size_t)b * 128 * EDIM;
    for (int r = 0; r < 128; ++r) {
        const float* row = base + (size_t)r * EDIM;
        float v0 = row[t];
        float v1 = row[t + 256];
        float v2 = row[t + 512];
        s0 += v0; q0 = fmaf(v0, v0, q0);
        s1 += v1; q1 = fmaf(v1, v1, q1);
        s2 += v2; q2 = fmaf(v2, v2, q2);
    }
    g_psum[b * EDIM + t]       = s0;  g_psqs[b * EDIM + t]       = q0;
    g_psum[b * EDIM + t + 256] = s1;  g_psqs[b * EDIM + t + 256] = q1;
    g_psum[b * EDIM + t + 512] = s2;  g_psqs[b * EDIM + t + 512] = q2;
}

__global__ void bn_finalize(const float* __restrict__ gamma,
                            const float* __restrict__ beta) {
    int c = blockIdx.x * blockDim.x + threadIdx.x;
    if (c >= EDIM) return;
    float s = 0.f, q = 0.f;
    for (int b = 0; b < 512; ++b) {
        s += g_psum[b * EDIM + c];
        q += g_psqs[b * EDIM + c];
    }
    const float inv_n = 1.f / (float)NROWS;
    float mean = s * inv_n;
    float var  = q * inv_n - mean * mean;
    float rstd = rsqrtf(var + 1e-5f);
    float g = gamma[c] * rstd;
    g_scale[c] = g;
    g_shift[c] = beta[c] - mean * g;
}

__global__ void __launch_bounds__(192) bn_sigmoid(float* __restrict__ OUT) {
    const int row = blockIdx.x;
    const int t   = threadIdx.x;
    float4* p = (float4*)(OUT + (size_t)row * EDIM) + t;
    float4 v  = *p;
    float4 sc = ((const float4*)g_scale)[t];
    float4 sh = ((const float4*)g_shift)[t];
    v.x = 1.f / (1.f + expf(-(fmaf(v.x, sc.x, sh.x))));
    v.y = 1.f / (1.f + expf(-(fmaf(v.y, sc.y, sh.y))));
    v.z = 1.f / (1.f + expf(-(fmaf(v.z, sc.z, sh.z))));
    v.w = 1.f / (1.f + expf(-(fmaf(v.w, sc.w, sh.w))));
    *p = v;
}

// ---------------------------------------------------------------------------
extern "C" void kernel_launch(void* const* d_in, const int* in_sizes, int n_in,
                              void* d_out, int out_size) {
    const float* x     = (const float*)d_in[0];
    const float* w1a   = (const float*)d_in[1];
    const float* w2a   = (const float*)d_in[2];
    const float* w1b   = (const float*)d_in[3];
    const float* w2b   = (const float*)d_in[4];
    const float* gamma = (const float*)d_in[5];
    const float* beta  = (const float*)d_in[6];
    float* out = (float*)d_out;

    cudaFuncSetAttribute(gemm_mma, cudaFuncAttributeMaxDynamicSharedMemorySize, SMEMB);

    build_L<<<768, 1024>>>(w1a, w2a);
    gemm_weights<<<dim3(EDIM / 64, 512 / 64), 256>>>(w1b, w2b);
    conv_B<<<(KDIM * EDIM) / 256, 256>>>();
    conv_A<<<NROWS / 4, 256>>>(x);
    gemm_mma<<<dim3(EDIM / 128, NROWS / 128), 256, SMEMB>>>(out);
    bn_partial<<<512, 256>>>(out);
    bn_finalize<<<3, 256>>>(gamma, beta);
    bn_sigmoid<<<NROWS, 192>>>(out);
}

// round 9
// speedup vs baseline: 3.4537x; 1.5038x over previous
#include <cuda_runtime.h>
#include <cuda_bf16.h>
#include <cuda_fp16.h>
#include <cstdint>

// ---------------------------------------------------------------------------
// out = sigmoid(BN( A @ M )),  A (65536 x 512) fp16 built from x, M (512x768)
// pre-combined.  GEMM: fp16 mma.sync m16n8k16, CTA 128x128, 8 warps, KB=64
// (8 iterations), 3-stage cp.async pipeline, XOR-swizzled smem, BN partial
// sums fused into the GEMM epilogue (deterministic per-CTA partials).
// ---------------------------------------------------------------------------

#define NROWS   65536
#define DIN     768
#define KDIM    512
#define EDIM    768

#define KB      64          // K per stage
#define NITER   (KDIM / KB) // 8

// smem stage: Af[128x64] fp16 (16KB) + Bf[128x64] fp16 (16KB), 128B rows,
// 16B-chunk XOR swizzle: off = r*128 + ((c ^ (r&7))<<4)
#define TERMB   16384
#define STG     32768
#define SMEMB   (3 * STG)   // 98304

// __device__ scratch (allocation-free rule)
__device__ __align__(16) float   g_L[512 * 1536];
__device__ __align__(16) float   g_M[KDIM * EDIM];
__device__ __align__(16) __half  g_Bf[EDIM * KDIM];          // [e][k]
__device__ __align__(16) __half  g_Af[(size_t)NROWS * KDIM]; // [n][k]
__device__ __align__(16) float   g_psum[512 * EDIM];
__device__ __align__(16) float   g_psqs[512 * EDIM];
__device__ __align__(16) float   g_scale[EDIM];
__device__ __align__(16) float   g_shift[EDIM];

// ---------------- PTX helpers (baseline sm_80+ features only) ---------------
__device__ __forceinline__ uint32_t smem_u32(const void* p) {
    uint32_t a;
    asm("{ .reg .u64 t; cvta.to.shared.u64 t, %1; cvt.u32.u64 %0, t; }" : "=r"(a) : "l"(p));
    return a;
}
__device__ __forceinline__ void cp16(uint32_t dst, const void* src) {
    asm volatile("cp.async.cg.shared.global [%0], [%1], 16;" :: "r"(dst), "l"(src) : "memory");
}
__device__ __forceinline__ void ldsm4(uint32_t* r, uint32_t a) {
    asm volatile("ldmatrix.sync.aligned.m8n8.x4.shared.b16 {%0,%1,%2,%3}, [%4];"
                 : "=r"(r[0]), "=r"(r[1]), "=r"(r[2]), "=r"(r[3]) : "r"(a));
}
__device__ __forceinline__ void mma_f16(float* c, const uint32_t* a,
                                        uint32_t b0, uint32_t b1) {
    asm volatile(
        "mma.sync.aligned.m16n8k16.row.col.f32.f16.f16.f32 "
        "{%0,%1,%2,%3}, {%4,%5,%6,%7}, {%8,%9}, {%0,%1,%2,%3};"
        : "+f"(c[0]), "+f"(c[1]), "+f"(c[2]), "+f"(c[3])
        : "r"(a[0]), "r"(a[1]), "r"(a[2]), "r"(a[3]), "r"(b0), "r"(b1));
}

// ---------------------------------------------------------------------------
// K0: build concatenated left matrix g_L (512 x 1536)   [proven]
// ---------------------------------------------------------------------------
__global__ void build_L(const float* __restrict__ w1a, const float* __restrict__ w2a) {
    int idx = blockIdx.x * blockDim.x + threadIdx.x;
    if (idx >= 512 * 1536) return;
    int i = idx / 1536;
    int j = idx % 1536;
    float v;
    if (j < 768) {
        v = (i < 256) ? w2a[i * 768 + j] : 0.5f * w1a[(i - 256) * 768 + j];
    } else {
        int jj = j - 768;
        v = (i < 256) ? 0.5f * w1a[i * 768 + jj]
                      : 0.5f * w2a[(i - 256) * 768 + jj] + 0.25f * w1a[(i - 256) * 768 + jj];
    }
    g_L[idx] = v;
}

// ---------------------------------------------------------------------------
// K1: g_M = g_L @ [w2b ; w1b]   fp32 exact   [proven]
// ---------------------------------------------------------------------------
__global__ void __launch_bounds__(256) gemm_weights(const float* __restrict__ w1b,
                                                    const float* __restrict__ w2b) {
    __shared__ __align__(16) float As[16][64];
    __shared__ __align__(16) float Bs[16][64];
    const int e0 = blockIdx.x * 64;
    const int i0 = blockIdx.y * 64;
    const int t  = threadIdx.x;
    const int tx = t & 15;
    const int ty = t >> 4;
    float acc[4][4] = {};

    for (int j0 = 0; j0 < 1536; j0 += 16) {
        {
            int r  = t >> 2;
            int jq = (t & 3) * 4;
            float4 v = *(const float4*)&g_L[(i0 + r) * 1536 + j0 + jq];
            As[jq + 0][r] = v.x; As[jq + 1][r] = v.y;
            As[jq + 2][r] = v.z; As[jq + 3][r] = v.w;
        }
        {
            int k  = t >> 4;
            int eq = (t & 15) * 4;
            int j  = j0 + k;
            const float* src = (j < 768) ? (w2b + (size_t)j * 768)
                                         : (w1b + (size_t)(j - 768) * 768);
            *(float4*)&Bs[k][eq] = *(const float4*)(src + e0 + eq);
        }
        __syncthreads();
        #pragma unroll
        for (int k = 0; k < 16; ++k) {
            float4 a = *(const float4*)&As[k][ty * 4];
            float4 b = *(const float4*)&Bs[k][tx * 4];
            float av[4] = {a.x, a.y, a.z, a.w};
            float bv[4] = {b.x, b.y, b.z, b.w};
            #pragma unroll
            for (int i = 0; i < 4; ++i)
                #pragma unroll
                for (int j = 0; j < 4; ++j)
                    acc[i][j] = fmaf(av[i], bv[j], acc[i][j]);
        }
        __syncthreads();
    }
    #pragma unroll
    for (int i = 0; i < 4; ++i)
        *(float4*)&g_M[(size_t)(i0 + ty * 4 + i) * EDIM + e0 + tx * 4] =
            make_float4(acc[i][0], acc[i][1], acc[i][2], acc[i][3]);
}

// ---------------------------------------------------------------------------
// K2: g_M -> g_Bf (fp16, [e][k] K-major transpose)
// ---------------------------------------------------------------------------
__global__ void __launch_bounds__(256) conv_B() {
    int idx = blockIdx.x * 256 + threadIdx.x;       // 512*768
    int e = idx % EDIM;
    int k = idx / EDIM;
    g_Bf[(size_t)e * KDIM + k] = __float2half_rn(g_M[(size_t)k * EDIM + e]);
}

// ---------------------------------------------------------------------------
// K3: x -> g_Af (fp16).  A(n,k) = x[n,0,k] (k<256) / x[n,1,..]+x[n,2,..]
// ---------------------------------------------------------------------------
__global__ void __launch_bounds__(256) conv_A(const float* __restrict__ X) {
    int id = blockIdx.x * 256 + threadIdx.x;        // NROWS*64 threads
    int n  = id >> 6;
    int k  = (id & 63) * 8;
    const float* p = X + (size_t)n * DIN + k;
    float4 v0 = *(const float4*)p;
    float4 v1 = *(const float4*)(p + 4);
    if (k >= 256) {
        float4 w0 = *(const float4*)(p + 256);
        float4 w1 = *(const float4*)(p + 260);
        v0.x += w0.x; v0.y += w0.y; v0.z += w0.z; v0.w += w0.w;
        v1.x += w1.x; v1.y += w1.y; v1.z += w1.z; v1.w += w1.w;
    }
    __half2 h0 = __float22half2_rn(make_float2(v0.x, v0.y));
    __half2 h1 = __float22half2_rn(make_float2(v0.z, v0.w));
    __half2 h2 = __float22half2_rn(make_float2(v1.x, v1.y));
    __half2 h3 = __float22half2_rn(make_float2(v1.z, v1.w));
    uint4 o;
    o.x = *(uint32_t*)&h0; o.y = *(uint32_t*)&h1;
    o.z = *(uint32_t*)&h2; o.w = *(uint32_t*)&h3;
    *(uint4*)(g_Af + (size_t)n * KDIM + k) = o;
}

// ---------------------------------------------------------------------------
// K4: main GEMM via fp16 mma.sync + fused BN partials.  grid (6, 512).
// ---------------------------------------------------------------------------
__device__ __forceinline__ void stage_issue(uint32_t st, int t, int n0, int e0, int k0) {
    #pragma unroll
    for (int j = 0; j < 8; ++j) {
        int idx  = t + 256 * j;          // 0..2047
        int part = idx >> 10;            // 0: A, 1: B
        int rr   = (idx >> 3) & 127;
        int c    = idx & 7;
        uint32_t dst = st + (uint32_t)(part * TERMB + rr * 128 + ((c ^ (rr & 7)) << 4));
        const __half* g = part ? g_Bf : g_Af;
        int base = part ? e0 : n0;
        cp16(dst, g + (size_t)(base + rr) * KDIM + k0 + c * 8);
    }
    asm volatile("cp.async.commit_group;" ::: "memory");
}

__global__ void __launch_bounds__(256, 2) gemm_mma(float* __restrict__ OUT) {
    extern __shared__ char smem[];
    const uint32_t sb = smem_u32(smem);
    const int t  = threadIdx.x;
    const int w  = t >> 5;
    const int l  = t & 31;
    const int mw = w & 1;                // M-warp (64 rows each)
    const int nw = w >> 1;               // N-warp (32 cols each)
    const int e0 = blockIdx.x * 128;
    const int n0 = blockIdx.y * 128;

    float acc[4][4][4];
    #pragma unroll
    for (int a = 0; a < 4; ++a)
        #pragma unroll
        for (int b = 0; b < 4; ++b)
            #pragma unroll
            for (int c = 0; c < 4; ++c) acc[a][b][c] = 0.f;

    // A ldsm rows: mw*64 + mt*16 + (l&15); chunk hi bit = l>>4
    uint32_t arow[4], amask[4];
    #pragma unroll
    for (int mt = 0; mt < 4; ++mt) {
        int row = mw * 64 + mt * 16 + (l & 15);
        arow[mt]  = (uint32_t)(row * 128);
        amask[mt] = (uint32_t)(row & 7);
    }
    const uint32_t ahi = (uint32_t)(l >> 4);          // 0/1
    // B ldsm rows: nw*32 + p*16 + ((l>>4)&1)*8 + (l&7); chunk hi = (l>>3)&1
    uint32_t brow[2], bmask[2];
    #pragma unroll
    for (int p = 0; p < 2; ++p) {
        int row = nw * 32 + p * 16 + ((l >> 4) & 1) * 8 + (l & 7);
        brow[p]  = (uint32_t)(row * 128);
        bmask[p] = (uint32_t)(row & 7);
    }
    const uint32_t bhi = (uint32_t)((l >> 3) & 1);

    stage_issue(sb + 0 * STG, t, n0, e0, 0);
    stage_issue(sb + 1 * STG, t, n0, e0, KB);

    int s = 0;
    #pragma unroll 1
    for (int i = 0; i < NITER; ++i) {
        if (i != NITER - 1) asm volatile("cp.async.wait_group 1;" ::: "memory");
        else                asm volatile("cp.async.wait_group 0;" ::: "memory");
        __syncthreads();

        const uint32_t stA = sb + (uint32_t)s * STG;
        const uint32_t stB = stA + TERMB;
        #pragma unroll
        for (int kk = 0; kk < 4; ++kk) {
            const uint32_t ch_a = (uint32_t)(kk * 2) + ahi;
            const uint32_t ch_b = (uint32_t)(kk * 2) + bhi;
            uint32_t Af[4][4], Bf[2][4];
            #pragma unroll
            for (int mt = 0; mt < 4; ++mt)
                ldsm4(Af[mt], stA + arow[mt] + ((ch_a ^ amask[mt]) << 4));
            #pragma unroll
            for (int p = 0; p < 2; ++p)
                ldsm4(Bf[p], stB + brow[p] + ((ch_b ^ bmask[p]) << 4));
            #pragma unroll
            for (int mt = 0; mt < 4; ++mt)
                #pragma unroll
                for (int nt = 0; nt < 4; ++nt) {
                    int p = nt >> 1, h = (nt & 1) * 2;
                    mma_f16(acc[mt][nt], Af[mt], Bf[p][h], Bf[p][h + 1]);
                }
        }

        if (i + 2 < NITER) {
            int s2 = s + 2; if (s2 >= 3) s2 -= 3;
            stage_issue(sb + (uint32_t)s2 * STG, t, n0, e0, (i + 2) * KB);
        }
        if (++s == 3) s = 0;
    }

    // ---- epilogue: store tile + fused BN partial sums -----------------------
    const int r0 = n0 + mw * 64;
    const int c0 = e0 + nw * 32;
    const int lr = l >> 2;
    const int lc = (l & 3) * 2;
    float cs[8], cq[8];
    #pragma unroll
    for (int j = 0; j < 8; ++j) { cs[j] = 0.f; cq[j] = 0.f; }

    #pragma unroll
    for (int mt = 0; mt < 4; ++mt)
        #pragma unroll
        for (int nt = 0; nt < 4; ++nt) {
            size_t o = (size_t)(r0 + mt * 16 + lr) * EDIM + c0 + nt * 8 + lc;
            float v0 = acc[mt][nt][0], v1 = acc[mt][nt][1];
            float v2 = acc[mt][nt][2], v3 = acc[mt][nt][3];
            *(float2*)(OUT + o)            = make_float2(v0, v1);
            *(float2*)(OUT + o + 8 * EDIM) = make_float2(v2, v3);
            cs[nt * 2 + 0] += v0 + v2;
            cs[nt * 2 + 1] += v1 + v3;
            cq[nt * 2 + 0] = fmaf(v0, v0, fmaf(v2, v2, cq[nt * 2 + 0]));
            cq[nt * 2 + 1] = fmaf(v1, v1, fmaf(v3, v3, cq[nt * 2 + 1]));
        }

    // deterministic in-CTA reduction over the 16 threads sharing each column
    __syncthreads();                                   // smem stages now free
    float* red_s = (float*)smem;                       // [16][128]
    float* red_q = (float*)(smem + 8192);              // [16][128]
    const int tid16 = mw * 8 + lr;                     // 0..15
    #pragma unroll
    for (int nt = 0; nt < 4; ++nt) {
        int colc = nw * 32 + nt * 8 + lc;
        red_s[tid16 * 128 + colc]     = cs[nt * 2 + 0];
        red_s[tid16 * 128 + colc + 1] = cs[nt * 2 + 1];
        red_q[tid16 * 128 + colc]     = cq[nt * 2 + 0];
        red_q[tid16 * 128 + colc + 1] = cq[nt * 2 + 1];
    }
    __syncthreads();
    if (t < 128) {
        float s = 0.f, q = 0.f;
        #pragma unroll
        for (int j = 0; j < 16; ++j) {
            s += red_s[j * 128 + t];
            q += red_q[j * 128 + t];
        }
        g_psum[(size_t)blockIdx.y * EDIM + e0 + t] = s;
        g_psqs[(size_t)blockIdx.y * EDIM + e0 + t] = q;
    }
}

// ---------------------------------------------------------------------------
// BN finalize + normalize/sigmoid
// ---------------------------------------------------------------------------
__global__ void bn_finalize(const float* __restrict__ gamma,
                            const float* __restrict__ beta) {
    int c = blockIdx.x * blockDim.x + threadIdx.x;
    if (c >= EDIM) return;
    float s = 0.f, q = 0.f;
    for (int b = 0; b < 512; ++b) {
        s += g_psum[b * EDIM + c];
        q += g_psqs[b * EDIM + c];
    }
    const float inv_n = 1.f / (float)NROWS;
    float mean = s * inv_n;
    float var  = q * inv_n - mean * mean;
    float rstd = rsqrtf(var + 1e-5f);
    float g = gamma[c] * rstd;
    g_scale[c] = g;
    g_shift[c] = beta[c] - mean * g;
}

__global__ void __launch_bounds__(192) bn_sigmoid(float* __restrict__ OUT) {
    const int row = blockIdx.x;
    const int t   = threadIdx.x;
    float4* p = (float4*)(OUT + (size_t)row * EDIM) + t;
    float4 v  = *p;
    float4 sc = ((const float4*)g_scale)[t];
    float4 sh = ((const float4*)g_shift)[t];
    v.x = 1.f / (1.f + expf(-(fmaf(v.x, sc.x, sh.x))));
    v.y = 1.f / (1.f + expf(-(fmaf(v.y, sc.y, sh.y))));
    v.z = 1.f / (1.f + expf(-(fmaf(v.z, sc.z, sh.z))));
    v.w = 1.f / (1.f + expf(-(fmaf(v.w, sc.w, sh.w))));
    *p = v;
}

// ---------------------------------------------------------------------------
extern "C" void kernel_launch(void* const* d_in, const int* in_sizes, int n_in,
                              void* d_out, int out_size) {
    const float* x     = (const float*)d_in[0];
    const float* w1a   = (const float*)d_in[1];
    const float* w2a   = (const float*)d_in[2];
    const float* w1b   = (const float*)d_in[3];
    const float* w2b   = (const float*)d_in[4];
    const float* gamma = (const float*)d_in[5];
    const float* beta  = (const float*)d_in[6];
    float* out = (float*)d_out;

    cudaFuncSetAttribute(gemm_mma, cudaFuncAttributeMaxDynamicSharedMemorySize, SMEMB);

    build_L<<<768, 1024>>>(w1a, w2a);
    gemm_weights<<<dim3(EDIM / 64, 512 / 64), 256>>>(w1b, w2b);
    conv_B<<<(KDIM * EDIM) / 256, 256>>>();
    conv_A<<<NROWS / 4, 256>>>(x);
    gemm_mma<<<dim3(EDIM / 128, NROWS / 128), 256, SMEMB>>>(out);
    bn_finalize<<<3, 256>>>(gamma, beta);
    bn_sigmoid<<<NROWS, 192>>>(out);
}

// round 10
// speedup vs baseline: 3.4974x; 1.0127x over previous
#include <cuda_runtime.h>
#include <cuda_bf16.h>
#include <cuda_fp16.h>
#include <cstdint>

// ---------------------------------------------------------------------------
// out = sigmoid(BN( A @ M )),  A (65536 x 512) fp16 built from x, M (512x768)
// pre-combined.  GEMM: fp16 mma.sync m16n8k16, CTA 128x128, 8 warps, KB=64,
// 3-stage cp.async pipeline, XOR-swizzled smem, BN partials fused in epilogue.
// R10: raw GEMM output stored fp16 (halves epilogue traffic); weight prep
// fused into a single kernel (L computed on the fly, fp16-T output direct).
// ---------------------------------------------------------------------------

#define NROWS   65536
#define DIN     768
#define KDIM    512
#define EDIM    768

#define KB      64          // K per stage
#define NITER   (KDIM / KB) // 8

// smem stage: Af[128x64] fp16 (16KB) + Bf[128x64] fp16 (16KB), 128B rows,
// 16B-chunk XOR swizzle: off = r*128 + ((c ^ (r&7))<<4)
#define TERMB   16384
#define STG     32768
#define SMEMB   (3 * STG)   // 98304

// __device__ scratch (allocation-free rule)
__device__ __align__(16) __half  g_Bf[EDIM * KDIM];            // [e][k]
__device__ __align__(16) __half  g_Af[(size_t)NROWS * KDIM];   // [n][k]
__device__ __align__(16) __half  g_raw[(size_t)NROWS * EDIM];  // fp16 raw out
__device__ __align__(16) float   g_psum[512 * EDIM];
__device__ __align__(16) float   g_psqs[512 * EDIM];
__device__ __align__(16) float   g_scale[EDIM];
__device__ __align__(16) float   g_shift[EDIM];

// ---------------- PTX helpers (baseline sm_80+ features only) ---------------
__device__ __forceinline__ uint32_t smem_u32(const void* p) {
    uint32_t a;
    asm("{ .reg .u64 t; cvta.to.shared.u64 t, %1; cvt.u32.u64 %0, t; }" : "=r"(a) : "l"(p));
    return a;
}
__device__ __forceinline__ void cp16(uint32_t dst, const void* src) {
    asm volatile("cp.async.cg.shared.global [%0], [%1], 16;" :: "r"(dst), "l"(src) : "memory");
}
__device__ __forceinline__ void ldsm4(uint32_t* r, uint32_t a) {
    asm volatile("ldmatrix.sync.aligned.m8n8.x4.shared.b16 {%0,%1,%2,%3}, [%4];"
                 : "=r"(r[0]), "=r"(r[1]), "=r"(r[2]), "=r"(r[3]) : "r"(a));
}
__device__ __forceinline__ void mma_f16(float* c, const uint32_t* a,
                                        uint32_t b0, uint32_t b1) {
    asm volatile(
        "mma.sync.aligned.m16n8k16.row.col.f32.f16.f16.f32 "
        "{%0,%1,%2,%3}, {%4,%5,%6,%7}, {%8,%9}, {%0,%1,%2,%3};"
        : "+f"(c[0]), "+f"(c[1]), "+f"(c[2]), "+f"(c[3])
        : "r"(a[0]), "r"(a[1]), "r"(a[2]), "r"(a[3]), "r"(b0), "r"(b1));
}

// ---------------------------------------------------------------------------
// K0: fused weight prep.  M = L @ [w2b ; w1b] with L(512x1536) computed on
// the fly from w1a/w2a; epilogue writes g_Bf = fp16(M^T) ([e][k]) directly.
// grid (12, 8), 256 threads, 64x64 tiles.
// ---------------------------------------------------------------------------
__global__ void __launch_bounds__(256) prep_B(const float* __restrict__ w1a,
                                              const float* __restrict__ w2a,
                                              const float* __restrict__ w1b,
                                              const float* __restrict__ w2b) {
    __shared__ __align__(16) float As[16][64];
    __shared__ __align__(16) float Bs[16][64];
    const int e0 = blockIdx.x * 64;
    const int i0 = blockIdx.y * 64;
    const int t  = threadIdx.x;
    const int tx = t & 15;
    const int ty = t >> 4;
    float acc[4][4] = {};

    for (int j0 = 0; j0 < 1536; j0 += 16) {
        {   // A tile: L(i0+r, j0+jq..+3) computed on the fly
            int r  = t >> 2;
            int jq = (t & 3) * 4;
            int i  = i0 + r;
            int j  = j0 + jq;
            float4 v;
            if (j < 768) {
                if (i < 256) {
                    v = *(const float4*)&w2a[(size_t)i * 768 + j];
                } else {
                    float4 a = *(const float4*)&w1a[(size_t)(i - 256) * 768 + j];
                    v = make_float4(0.5f * a.x, 0.5f * a.y, 0.5f * a.z, 0.5f * a.w);
                }
            } else {
                int jj = j - 768;
                if (i < 256) {
                    float4 a = *(const float4*)&w1a[(size_t)i * 768 + jj];
                    v = make_float4(0.5f * a.x, 0.5f * a.y, 0.5f * a.z, 0.5f * a.w);
                } else {
                    float4 a = *(const float4*)&w2a[(size_t)(i - 256) * 768 + jj];
                    float4 b = *(const float4*)&w1a[(size_t)(i - 256) * 768 + jj];
                    v = make_float4(fmaf(0.25f, b.x, 0.5f * a.x),
                                    fmaf(0.25f, b.y, 0.5f * a.y),
                                    fmaf(0.25f, b.z, 0.5f * a.z),
                                    fmaf(0.25f, b.w, 0.5f * a.w));
                }
            }
            As[jq + 0][r] = v.x; As[jq + 1][r] = v.y;
            As[jq + 2][r] = v.z; As[jq + 3][r] = v.w;
        }
        {   // B tile: [w2b ; w1b](j0+k, e0+eq..)
            int k  = t >> 4;
            int eq = (t & 15) * 4;
            int j  = j0 + k;
            const float* src = (j < 768) ? (w2b + (size_t)j * 768)
                                         : (w1b + (size_t)(j - 768) * 768);
            *(float4*)&Bs[k][eq] = *(const float4*)(src + e0 + eq);
        }
        __syncthreads();
        #pragma unroll
        for (int k = 0; k < 16; ++k) {
            float4 a = *(const float4*)&As[k][ty * 4];
            float4 b = *(const float4*)&Bs[k][tx * 4];
            float av[4] = {a.x, a.y, a.z, a.w};
            float bv[4] = {b.x, b.y, b.z, b.w};
            #pragma unroll
            for (int i = 0; i < 4; ++i)
                #pragma unroll
                for (int j = 0; j < 4; ++j)
                    acc[i][j] = fmaf(av[i], bv[j], acc[i][j]);
        }
        __syncthreads();
    }
    // epilogue: g_Bf[e][k] = fp16(M[k][e])  (transposed, K-major)
    #pragma unroll
    for (int i = 0; i < 4; ++i) {
        int k = i0 + ty * 4 + i;
        #pragma unroll
        for (int j = 0; j < 4; ++j) {
            int e = e0 + tx * 4 + j;
            g_Bf[(size_t)e * KDIM + k] = __float2half_rn(acc[i][j]);
        }
    }
}

// ---------------------------------------------------------------------------
// K1: x -> g_Af (fp16).  A(n,k) = x[n,0,k] (k<256) / x[n,1,..]+x[n,2,..]
// ---------------------------------------------------------------------------
__global__ void __launch_bounds__(256) conv_A(const float* __restrict__ X) {
    int id = blockIdx.x * 256 + threadIdx.x;        // NROWS*64 threads
    int n  = id >> 6;
    int k  = (id & 63) * 8;
    const float* p = X + (size_t)n * DIN + k;
    float4 v0 = *(const float4*)p;
    float4 v1 = *(const float4*)(p + 4);
    if (k >= 256) {
        float4 w0 = *(const float4*)(p + 256);
        float4 w1 = *(const float4*)(p + 260);
        v0.x += w0.x; v0.y += w0.y; v0.z += w0.z; v0.w += w0.w;
        v1.x += w1.x; v1.y += w1.y; v1.z += w1.z; v1.w += w1.w;
    }
    __half2 h0 = __float22half2_rn(make_float2(v0.x, v0.y));
    __half2 h1 = __float22half2_rn(make_float2(v0.z, v0.w));
    __half2 h2 = __float22half2_rn(make_float2(v1.x, v1.y));
    __half2 h3 = __float22half2_rn(make_float2(v1.z, v1.w));
    uint4 o;
    o.x = *(uint32_t*)&h0; o.y = *(uint32_t*)&h1;
    o.z = *(uint32_t*)&h2; o.w = *(uint32_t*)&h3;
    *(uint4*)(g_Af + (size_t)n * KDIM + k) = o;
}

// ---------------------------------------------------------------------------
// K2: main GEMM via fp16 mma.sync + fused BN partials.  grid (6, 512).
// Raw output stored fp16 to g_raw.
// ---------------------------------------------------------------------------
__device__ __forceinline__ void stage_issue(uint32_t st, int t, int n0, int e0, int k0) {
    #pragma unroll
    for (int j = 0; j < 8; ++j) {
        int idx  = t + 256 * j;          // 0..2047
        int part = idx >> 10;            // 0: A, 1: B
        int rr   = (idx >> 3) & 127;
        int c    = idx & 7;
        uint32_t dst = st + (uint32_t)(part * TERMB + rr * 128 + ((c ^ (rr & 7)) << 4));
        const __half* g = part ? g_Bf : g_Af;
        int base = part ? e0 : n0;
        cp16(dst, g + (size_t)(base + rr) * KDIM + k0 + c * 8);
    }
    asm volatile("cp.async.commit_group;" ::: "memory");
}

__global__ void __launch_bounds__(256, 2) gemm_mma() {
    extern __shared__ char smem[];
    const uint32_t sb = smem_u32(smem);
    const int t  = threadIdx.x;
    const int w  = t >> 5;
    const int l  = t & 31;
    const int mw = w & 1;                // M-warp (64 rows each)
    const int nw = w >> 1;               // N-warp (32 cols each)
    const int e0 = blockIdx.x * 128;
    const int n0 = blockIdx.y * 128;

    float acc[4][4][4];
    #pragma unroll
    for (int a = 0; a < 4; ++a)
        #pragma unroll
        for (int b = 0; b < 4; ++b)
            #pragma unroll
            for (int c = 0; c < 4; ++c) acc[a][b][c] = 0.f;

    uint32_t arow[4], amask[4];
    #pragma unroll
    for (int mt = 0; mt < 4; ++mt) {
        int row = mw * 64 + mt * 16 + (l & 15);
        arow[mt]  = (uint32_t)(row * 128);
        amask[mt] = (uint32_t)(row & 7);
    }
    const uint32_t ahi = (uint32_t)(l >> 4);
    uint32_t brow[2], bmask[2];
    #pragma unroll
    for (int p = 0; p < 2; ++p) {
        int row = nw * 32 + p * 16 + ((l >> 4) & 1) * 8 + (l & 7);
        brow[p]  = (uint32_t)(row * 128);
        bmask[p] = (uint32_t)(row & 7);
    }
    const uint32_t bhi = (uint32_t)((l >> 3) & 1);

    stage_issue(sb + 0 * STG, t, n0, e0, 0);
    stage_issue(sb + 1 * STG, t, n0, e0, KB);

    int s = 0;
    #pragma unroll 1
    for (int i = 0; i < NITER; ++i) {
        if (i != NITER - 1) asm volatile("cp.async.wait_group 1;" ::: "memory");
        else                asm volatile("cp.async.wait_group 0;" ::: "memory");
        __syncthreads();

        const uint32_t stA = sb + (uint32_t)s * STG;
        const uint32_t stB = stA + TERMB;
        #pragma unroll
        for (int kk = 0; kk < 4; ++kk) {
            const uint32_t ch_a = (uint32_t)(kk * 2) + ahi;
            const uint32_t ch_b = (uint32_t)(kk * 2) + bhi;
            uint32_t Af[4][4], Bf[2][4];
            #pragma unroll
            for (int mt = 0; mt < 4; ++mt)
                ldsm4(Af[mt], stA + arow[mt] + ((ch_a ^ amask[mt]) << 4));
            #pragma unroll
            for (int p = 0; p < 2; ++p)
                ldsm4(Bf[p], stB + brow[p] + ((ch_b ^ bmask[p]) << 4));
            #pragma unroll
            for (int mt = 0; mt < 4; ++mt)
                #pragma unroll
                for (int nt = 0; nt < 4; ++nt) {
                    int p = nt >> 1, h = (nt & 1) * 2;
                    mma_f16(acc[mt][nt], Af[mt], Bf[p][h], Bf[p][h + 1]);
                }
        }

        if (i + 2 < NITER) {
            int s2 = s + 2; if (s2 >= 3) s2 -= 3;
            stage_issue(sb + (uint32_t)s2 * STG, t, n0, e0, (i + 2) * KB);
        }
        if (++s == 3) s = 0;
    }

    // ---- epilogue: store fp16 raw tile + fused BN partial sums --------------
    const int r0 = n0 + mw * 64;
    const int c0 = e0 + nw * 32;
    const int lr = l >> 2;
    const int lc = (l & 3) * 2;
    float cs[8], cq[8];
    #pragma unroll
    for (int j = 0; j < 8; ++j) { cs[j] = 0.f; cq[j] = 0.f; }

    #pragma unroll
    for (int mt = 0; mt < 4; ++mt)
        #pragma unroll
        for (int nt = 0; nt < 4; ++nt) {
            size_t o = (size_t)(r0 + mt * 16 + lr) * EDIM + c0 + nt * 8 + lc;
            float v0 = acc[mt][nt][0], v1 = acc[mt][nt][1];
            float v2 = acc[mt][nt][2], v3 = acc[mt][nt][3];
            *(__half2*)(g_raw + o)            = __floats2half2_rn(v0, v1);
            *(__half2*)(g_raw + o + 8 * EDIM) = __floats2half2_rn(v2, v3);
            cs[nt * 2 + 0] += v0 + v2;
            cs[nt * 2 + 1] += v1 + v3;
            cq[nt * 2 + 0] = fmaf(v0, v0, fmaf(v2, v2, cq[nt * 2 + 0]));
            cq[nt * 2 + 1] = fmaf(v1, v1, fmaf(v3, v3, cq[nt * 2 + 1]));
        }

    // deterministic in-CTA reduction over the 16 threads sharing each column
    __syncthreads();                                   // smem stages now free
    float* red_s = (float*)smem;                       // [16][128]
    float* red_q = (float*)(smem + 8192);              // [16][128]
    const int tid16 = mw * 8 + lr;                     // 0..15
    #pragma unroll
    for (int nt = 0; nt < 4; ++nt) {
        int colc = nw * 32 + nt * 8 + lc;
        red_s[tid16 * 128 + colc]     = cs[nt * 2 + 0];
        red_s[tid16 * 128 + colc + 1] = cs[nt * 2 + 1];
        red_q[tid16 * 128 + colc]     = cq[nt * 2 + 0];
        red_q[tid16 * 128 + colc + 1] = cq[nt * 2 + 1];
    }
    __syncthreads();
    if (t < 128) {
        float s = 0.f, q = 0.f;
        #pragma unroll
        for (int j = 0; j < 16; ++j) {
            s += red_s[j * 128 + t];
            q += red_q[j * 128 + t];
        }
        g_psum[(size_t)blockIdx.y * EDIM + e0 + t] = s;
        g_psqs[(size_t)blockIdx.y * EDIM + e0 + t] = q;
    }
}

// ---------------------------------------------------------------------------
// BN finalize + normalize/sigmoid (reads fp16 raw, writes fp32 out)
// ---------------------------------------------------------------------------
__global__ void bn_finalize(const float* __restrict__ gamma,
                            const float* __restrict__ beta) {
    int c = blockIdx.x * blockDim.x + threadIdx.x;
    if (c >= EDIM) return;
    float s = 0.f, q = 0.f;
    for (int b = 0; b < 512; ++b) {
        s += g_psum[b * EDIM + c];
        q += g_psqs[b * EDIM + c];
    }
    const float inv_n = 1.f / (float)NROWS;
    float mean = s * inv_n;
    float var  = q * inv_n - mean * mean;
    float rstd = rsqrtf(var + 1e-5f);
    float g = gamma[c] * rstd;
    g_scale[c] = g;
    g_shift[c] = beta[c] - mean * g;
}

__global__ void __launch_bounds__(192) bn_sigmoid(float* __restrict__ OUT) {
    const int row = blockIdx.x;
    const int t   = threadIdx.x;                       // cols t*4..t*4+3
    uint2 rv = *(const uint2*)(g_raw + (size_t)row * EDIM + t * 4);
    __half2 h0 = *(__half2*)&rv.x;
    __half2 h1 = *(__half2*)&rv.y;
    float2 f0 = __half22float2(h0);
    float2 f1 = __half22float2(h1);
    float4 sc = ((const float4*)g_scale)[t];
    float4 sh = ((const float4*)g_shift)[t];
    float4 v;
    v.x = 1.f / (1.f + expf(-(fmaf(f0.x, sc.x, sh.x))));
    v.y = 1.f / (1.f + expf(-(fmaf(f0.y, sc.y, sh.y))));
    v.z = 1.f / (1.f + expf(-(fmaf(f1.x, sc.z, sh.z))));
    v.w = 1.f / (1.f + expf(-(fmaf(f1.y, sc.w, sh.w))));
    ((float4*)(OUT + (size_t)row * EDIM))[t] = v;
}

// ---------------------------------------------------------------------------
extern "C" void kernel_launch(void* const* d_in, const int* in_sizes, int n_in,
                              void* d_out, int out_size) {
    const float* x     = (const float*)d_in[0];
    const float* w1a   = (const float*)d_in[1];
    const float* w2a   = (const float*)d_in[2];
    const float* w1b   = (const float*)d_in[3];
    const float* w2b   = (const float*)d_in[4];
    const float* gamma = (const float*)d_in[5];
    const float* beta  = (const float*)d_in[6];
    float* out = (float*)d_out;

    cudaFuncSetAttribute(gemm_mma, cudaFuncAttributeMaxDynamicSharedMemorySize, SMEMB);

    prep_B<<<dim3(EDIM / 64, 512 / 64), 256>>>(w1a, w2a, w1b, w2b);
    conv_A<<<NROWS / 4, 256>>>(x);
    gemm_mma<<<dim3(EDIM / 128, NROWS / 128), 256, SMEMB>>>();
    bn_finalize<<<3, 256>>>(gamma, beta);
    bn_sigmoid<<<NROWS, 192>>>(out);
}

// round 11
// speedup vs baseline: 3.7765x; 1.0798x over previous
#include <cuda_runtime.h>
#include <cuda_bf16.h>
#include <cuda_fp16.h>
#include <cstdint>

// ---------------------------------------------------------------------------
// out = sigmoid(BN( A @ M )),  A (65536 x 512) fp16 built from x, M (512x768)
// pre-combined.  GEMM: fp16 mma.sync m16n8k16, CTA 128x128, 8 warps, KB=64,
// 3-stage cp.async pipeline, XOR-swizzled smem, BN partials fused in epilogue.
// R11: psum layout transposed to [col][512]; bn_finalize is warp-per-column
// (was grid=3 latency-bound at 45.8us -> ~3us).
// ---------------------------------------------------------------------------

#define NROWS   65536
#define DIN     768
#define KDIM    512
#define EDIM    768

#define KB      64          // K per stage
#define NITER   (KDIM / KB) // 8

// smem stage: Af[128x64] fp16 (16KB) + Bf[128x64] fp16 (16KB), 128B rows,
// 16B-chunk XOR swizzle: off = r*128 + ((c ^ (r&7))<<4)
#define TERMB   16384
#define STG     32768
#define SMEMB   (3 * STG)   // 98304

// __device__ scratch (allocation-free rule)
__device__ __align__(16) __half  g_Bf[EDIM * KDIM];            // [e][k]
__device__ __align__(16) __half  g_Af[(size_t)NROWS * KDIM];   // [n][k]
__device__ __align__(16) __half  g_raw[(size_t)NROWS * EDIM];  // fp16 raw out
__device__ __align__(16) float   g_psum[EDIM * 512];           // [col][rowblk]
__device__ __align__(16) float   g_psqs[EDIM * 512];
__device__ __align__(16) float   g_scale[EDIM];
__device__ __align__(16) float   g_shift[EDIM];

// ---------------- PTX helpers (baseline sm_80+ features only) ---------------
__device__ __forceinline__ uint32_t smem_u32(const void* p) {
    uint32_t a;
    asm("{ .reg .u64 t; cvta.to.shared.u64 t, %1; cvt.u32.u64 %0, t; }" : "=r"(a) : "l"(p));
    return a;
}
__device__ __forceinline__ void cp16(uint32_t dst, const void* src) {
    asm volatile("cp.async.cg.shared.global [%0], [%1], 16;" :: "r"(dst), "l"(src) : "memory");
}
__device__ __forceinline__ void ldsm4(uint32_t* r, uint32_t a) {
    asm volatile("ldmatrix.sync.aligned.m8n8.x4.shared.b16 {%0,%1,%2,%3}, [%4];"
                 : "=r"(r[0]), "=r"(r[1]), "=r"(r[2]), "=r"(r[3]) : "r"(a));
}
__device__ __forceinline__ void mma_f16(float* c, const uint32_t* a,
                                        uint32_t b0, uint32_t b1) {
    asm volatile(
        "mma.sync.aligned.m16n8k16.row.col.f32.f16.f16.f32 "
        "{%0,%1,%2,%3}, {%4,%5,%6,%7}, {%8,%9}, {%0,%1,%2,%3};"
        : "+f"(c[0]), "+f"(c[1]), "+f"(c[2]), "+f"(c[3])
        : "r"(a[0]), "r"(a[1]), "r"(a[2]), "r"(a[3]), "r"(b0), "r"(b1));
}

// ---------------------------------------------------------------------------
// K0: fused weight prep.  M = L @ [w2b ; w1b] with L(512x1536) computed on
// the fly; epilogue writes g_Bf = fp16(M^T) ([e][k]) directly.   [proven]
// ---------------------------------------------------------------------------
__global__ void __launch_bounds__(256) prep_B(const float* __restrict__ w1a,
                                              const float* __restrict__ w2a,
                                              const float* __restrict__ w1b,
                                              const float* __restrict__ w2b) {
    __shared__ __align__(16) float As[16][64];
    __shared__ __align__(16) float Bs[16][64];
    const int e0 = blockIdx.x * 64;
    const int i0 = blockIdx.y * 64;
    const int t  = threadIdx.x;
    const int tx = t & 15;
    const int ty = t >> 4;
    float acc[4][4] = {};

    for (int j0 = 0; j0 < 1536; j0 += 16) {
        {   // A tile: L(i0+r, j0+jq..+3) computed on the fly
            int r  = t >> 2;
            int jq = (t & 3) * 4;
            int i  = i0 + r;
            int j  = j0 + jq;
            float4 v;
            if (j < 768) {
                if (i < 256) {
                    v = *(const float4*)&w2a[(size_t)i * 768 + j];
                } else {
                    float4 a = *(const float4*)&w1a[(size_t)(i - 256) * 768 + j];
                    v = make_float4(0.5f * a.x, 0.5f * a.y, 0.5f * a.z, 0.5f * a.w);
                }
            } else {
                int jj = j - 768;
                if (i < 256) {
                    float4 a = *(const float4*)&w1a[(size_t)i * 768 + jj];
                    v = make_float4(0.5f * a.x, 0.5f * a.y, 0.5f * a.z, 0.5f * a.w);
                } else {
                    float4 a = *(const float4*)&w2a[(size_t)(i - 256) * 768 + jj];
                    float4 b = *(const float4*)&w1a[(size_t)(i - 256) * 768 + jj];
                    v = make_float4(fmaf(0.25f, b.x, 0.5f * a.x),
                                    fmaf(0.25f, b.y, 0.5f * a.y),
                                    fmaf(0.25f, b.z, 0.5f * a.z),
                                    fmaf(0.25f, b.w, 0.5f * a.w));
                }
            }
            As[jq + 0][r] = v.x; As[jq + 1][r] = v.y;
            As[jq + 2][r] = v.z; As[jq + 3][r] = v.w;
        }
        {   // B tile: [w2b ; w1b](j0+k, e0+eq..)
            int k  = t >> 4;
            int eq = (t & 15) * 4;
            int j  = j0 + k;
            const float* src = (j < 768) ? (w2b + (size_t)j * 768)
                                         : (w1b + (size_t)(j - 768) * 768);
            *(float4*)&Bs[k][eq] = *(const float4*)(src + e0 + eq);
        }
        __syncthreads();
        #pragma unroll
        for (int k = 0; k < 16; ++k) {
            float4 a = *(const float4*)&As[k][ty * 4];
            float4 b = *(const float4*)&Bs[k][tx * 4];
            float av[4] = {a.x, a.y, a.z, a.w};
            float bv[4] = {b.x, b.y, b.z, b.w};
            #pragma unroll
            for (int i = 0; i < 4; ++i)
                #pragma unroll
                for (int j = 0; j < 4; ++j)
                    acc[i][j] = fmaf(av[i], bv[j], acc[i][j]);
        }
        __syncthreads();
    }
    #pragma unroll
    for (int i = 0; i < 4; ++i) {
        int k = i0 + ty * 4 + i;
        #pragma unroll
        for (int j = 0; j < 4; ++j) {
            int e = e0 + tx * 4 + j;
            g_Bf[(size_t)e * KDIM + k] = __float2half_rn(acc[i][j]);
        }
    }
}

// ---------------------------------------------------------------------------
// K1: x -> g_Af (fp16).  A(n,k) = x[n,0,k] (k<256) / x[n,1,..]+x[n,2,..]
// ---------------------------------------------------------------------------
__global__ void __launch_bounds__(256) conv_A(const float* __restrict__ X) {
    int id = blockIdx.x * 256 + threadIdx.x;        // NROWS*64 threads
    int n  = id >> 6;
    int k  = (id & 63) * 8;
    const float* p = X + (size_t)n * DIN + k;
    float4 v0 = *(const float4*)p;
    float4 v1 = *(const float4*)(p + 4);
    if (k >= 256) {
        float4 w0 = *(const float4*)(p + 256);
        float4 w1 = *(const float4*)(p + 260);
        v0.x += w0.x; v0.y += w0.y; v0.z += w0.z; v0.w += w0.w;
        v1.x += w1.x; v1.y += w1.y; v1.z += w1.z; v1.w += w1.w;
    }
    __half2 h0 = __float22half2_rn(make_float2(v0.x, v0.y));
    __half2 h1 = __float22half2_rn(make_float2(v0.z, v0.w));
    __half2 h2 = __float22half2_rn(make_float2(v1.x, v1.y));
    __half2 h3 = __float22half2_rn(make_float2(v1.z, v1.w));
    uint4 o;
    o.x = *(uint32_t*)&h0; o.y = *(uint32_t*)&h1;
    o.z = *(uint32_t*)&h2; o.w = *(uint32_t*)&h3;
    *(uint4*)(g_Af + (size_t)n * KDIM + k) = o;
}

// ---------------------------------------------------------------------------
// K2: main GEMM via fp16 mma.sync + fused BN partials.  grid (6, 512).
// ---------------------------------------------------------------------------
__device__ __forceinline__ void stage_issue(uint32_t st, int t, int n0, int e0, int k0) {
    #pragma unroll
    for (int j = 0; j < 8; ++j) {
        int idx  = t + 256 * j;          // 0..2047
        int part = idx >> 10;            // 0: A, 1: B
        int rr   = (idx >> 3) & 127;
        int c    = idx & 7;
        uint32_t dst = st + (uint32_t)(part * TERMB + rr * 128 + ((c ^ (rr & 7)) << 4));
        const __half* g = part ? g_Bf : g_Af;
        int base = part ? e0 : n0;
        cp16(dst, g + (size_t)(base + rr) * KDIM + k0 + c * 8);
    }
    asm volatile("cp.async.commit_group;" ::: "memory");
}

__global__ void __launch_bounds__(256, 2) gemm_mma() {
    extern __shared__ char smem[];
    const uint32_t sb = smem_u32(smem);
    const int t  = threadIdx.x;
    const int w  = t >> 5;
    const int l  = t & 31;
    const int mw = w & 1;                // M-warp (64 rows each)
    const int nw = w >> 1;               // N-warp (32 cols each)
    const int e0 = blockIdx.x * 128;
    const int n0 = blockIdx.y * 128;

    float acc[4][4][4];
    #pragma unroll
    for (int a = 0; a < 4; ++a)
        #pragma unroll
        for (int b = 0; b < 4; ++b)
            #pragma unroll
            for (int c = 0; c < 4; ++c) acc[a][b][c] = 0.f;

    uint32_t arow[4], amask[4];
    #pragma unroll
    for (int mt = 0; mt < 4; ++mt) {
        int row = mw * 64 + mt * 16 + (l & 15);
        arow[mt]  = (uint32_t)(row * 128);
        amask[mt] = (uint32_t)(row & 7);
    }
    const uint32_t ahi = (uint32_t)(l >> 4);
    uint32_t brow[2], bmask[2];
    #pragma unroll
    for (int p = 0; p < 2; ++p) {
        int row = nw * 32 + p * 16 + ((l >> 4) & 1) * 8 + (l & 7);
        brow[p]  = (uint32_t)(row * 128);
        bmask[p] = (uint32_t)(row & 7);
    }
    const uint32_t bhi = (uint32_t)((l >> 3) & 1);

    stage_issue(sb + 0 * STG, t, n0, e0, 0);
    stage_issue(sb + 1 * STG, t, n0, e0, KB);

    int s = 0;
    #pragma unroll 1
    for (int i = 0; i < NITER; ++i) {
        if (i != NITER - 1) asm volatile("cp.async.wait_group 1;" ::: "memory");
        else                asm volatile("cp.async.wait_group 0;" ::: "memory");
        __syncthreads();

        const uint32_t stA = sb + (uint32_t)s * STG;
        const uint32_t stB = stA + TERMB;
        #pragma unroll
        for (int kk = 0; kk < 4; ++kk) {
            const uint32_t ch_a = (uint32_t)(kk * 2) + ahi;
            const uint32_t ch_b = (uint32_t)(kk * 2) + bhi;
            uint32_t Af[4][4], Bf[2][4];
            #pragma unroll
            for (int mt = 0; mt < 4; ++mt)
                ldsm4(Af[mt], stA + arow[mt] + ((ch_a ^ amask[mt]) << 4));
            #pragma unroll
            for (int p = 0; p < 2; ++p)
                ldsm4(Bf[p], stB + brow[p] + ((ch_b ^ bmask[p]) << 4));
            #pragma unroll
            for (int mt = 0; mt < 4; ++mt)
                #pragma unroll
                for (int nt = 0; nt < 4; ++nt) {
                    int p = nt >> 1, h = (nt & 1) * 2;
                    mma_f16(acc[mt][nt], Af[mt], Bf[p][h], Bf[p][h + 1]);
                }
        }

        if (i + 2 < NITER) {
            int s2 = s + 2; if (s2 >= 3) s2 -= 3;
            stage_issue(sb + (uint32_t)s2 * STG, t, n0, e0, (i + 2) * KB);
        }
        if (++s == 3) s = 0;
    }

    // ---- epilogue: store fp16 raw tile + fused BN partial sums --------------
    const int r0 = n0 + mw * 64;
    const int c0 = e0 + nw * 32;
    const int lr = l >> 2;
    const int lc = (l & 3) * 2;
    float cs[8], cq[8];
    #pragma unroll
    for (int j = 0; j < 8; ++j) { cs[j] = 0.f; cq[j] = 0.f; }

    #pragma unroll
    for (int mt = 0; mt < 4; ++mt)
        #pragma unroll
        for (int nt = 0; nt < 4; ++nt) {
            size_t o = (size_t)(r0 + mt * 16 + lr) * EDIM + c0 + nt * 8 + lc;
            float v0 = acc[mt][nt][0], v1 = acc[mt][nt][1];
            float v2 = acc[mt][nt][2], v3 = acc[mt][nt][3];
            *(__half2*)(g_raw + o)            = __floats2half2_rn(v0, v1);
            *(__half2*)(g_raw + o + 8 * EDIM) = __floats2half2_rn(v2, v3);
            cs[nt * 2 + 0] += v0 + v2;
            cs[nt * 2 + 1] += v1 + v3;
            cq[nt * 2 + 0] = fmaf(v0, v0, fmaf(v2, v2, cq[nt * 2 + 0]));
            cq[nt * 2 + 1] = fmaf(v1, v1, fmaf(v3, v3, cq[nt * 2 + 1]));
        }

    // deterministic in-CTA reduction over the 16 threads sharing each column
    __syncthreads();                                   // smem stages now free
    float* red_s = (float*)smem;                       // [16][128]
    float* red_q = (float*)(smem + 8192);              // [16][128]
    const int tid16 = mw * 8 + lr;                     // 0..15
    #pragma unroll
    for (int nt = 0; nt < 4; ++nt) {
        int colc = nw * 32 + nt * 8 + lc;
        red_s[tid16 * 128 + colc]     = cs[nt * 2 + 0];
        red_s[tid16 * 128 + colc + 1] = cs[nt * 2 + 1];
        red_q[tid16 * 128 + colc]     = cq[nt * 2 + 0];
        red_q[tid16 * 128 + colc + 1] = cq[nt * 2 + 1];
    }
    __syncthreads();
    if (t < 128) {
        float s = 0.f, q = 0.f;
        #pragma unroll
        for (int j = 0; j < 16; ++j) {
            s += red_s[j * 128 + t];
            q += red_q[j * 128 + t];
        }
        // transposed layout: [col][rowblock]  (contiguous per column)
        g_psum[(size_t)(e0 + t) * 512 + blockIdx.y] = s;
        g_psqs[(size_t)(e0 + t) * 512 + blockIdx.y] = q;
    }
}

// ---------------------------------------------------------------------------
// K3: bn_finalize — one warp per column, coalesced contiguous reads.
// grid 96 x 256 threads (8 warps/block, 768 warps total).
// ---------------------------------------------------------------------------
__global__ void __launch_bounds__(256) bn_finalize(const float* __restrict__ gamma,
                                                   const float* __restrict__ beta) {
    const int wid = threadIdx.x >> 5;
    const int l   = threadIdx.x & 31;
    const int c   = blockIdx.x * 8 + wid;          // 0..767
    const float* ps = g_psum + (size_t)c * 512;
    const float* pq = g_psqs + (size_t)c * 512;
    float s = 0.f, q = 0.f;
    #pragma unroll
    for (int j = 0; j < 16; ++j) {
        s += ps[l + 32 * j];
        q += pq[l + 32 * j];
    }
    #pragma unroll
    for (int d = 16; d > 0; d >>= 1) {
        s += __shfl_xor_sync(0xFFFFFFFF, s, d);
        q += __shfl_xor_sync(0xFFFFFFFF, q, d);
    }
    if (l == 0) {
        const float inv_n = 1.f / (float)NROWS;
        float mean = s * inv_n;
        float var  = q * inv_n - mean * mean;
        float rstd = rsqrtf(var + 1e-5f);
        float g = gamma[c] * rstd;
        g_scale[c] = g;
        g_shift[c] = beta[c] - mean * g;
    }
}

// ---------------------------------------------------------------------------
// K4: normalize + sigmoid (reads fp16 raw, writes fp32 out)
// ---------------------------------------------------------------------------
__global__ void __launch_bounds__(192) bn_sigmoid(float* __restrict__ OUT) {
    const int row = blockIdx.x;
    const int t   = threadIdx.x;                       // cols t*4..t*4+3
    uint2 rv = *(const uint2*)(g_raw + (size_t)row * EDIM + t * 4);
    __half2 h0 = *(__half2*)&rv.x;
    __half2 h1 = *(__half2*)&rv.y;
    float2 f0 = __half22float2(h0);
    float2 f1 = __half22float2(h1);
    float4 sc = ((const float4*)g_scale)[t];
    float4 sh = ((const float4*)g_shift)[t];
    float4 v;
    v.x = 1.f / (1.f + expf(-(fmaf(f0.x, sc.x, sh.x))));
    v.y = 1.f / (1.f + expf(-(fmaf(f0.y, sc.y, sh.y))));
    v.z = 1.f / (1.f + expf(-(fmaf(f1.x, sc.z, sh.z))));
    v.w = 1.f / (1.f + expf(-(fmaf(f1.y, sc.w, sh.w))));
    ((float4*)(OUT + (size_t)row * EDIM))[t] = v;
}

// ---------------------------------------------------------------------------
extern "C" void kernel_launch(void* const* d_in, const int* in_sizes, int n_in,
                              void* d_out, int out_size) {
    const float* x     = (const float*)d_in[0];
    const float* w1a   = (const float*)d_in[1];
    const float* w2a   = (const float*)d_in[2];
    const float* w1b   = (const float*)d_in[3];
    const float* w2b   = (const float*)d_in[4];
    const float* gamma = (const float*)d_in[5];
    const float* beta  = (const float*)d_in[6];
    float* out = (float*)d_out;

    cudaFuncSetAttribute(gemm_mma, cudaFuncAttributeMaxDynamicSharedMemorySize, SMEMB);

    prep_B<<<dim3(EDIM / 64, 512 / 64), 256>>>(w1a, w2a, w1b, w2b);
    conv_A<<<NROWS / 4, 256>>>(x);
    gemm_mma<<<dim3(EDIM / 128, NROWS / 128), 256, SMEMB>>>();
    bn_finalize<<<96, 256>>>(gamma, beta);
    bn_sigmoid<<<NROWS, 192>>>(out);
}

// round 12
// speedup vs baseline: 4.4269x; 1.1722x over previous
#include <cuda_runtime.h>
#include <cuda_bf16.h>
#include <cuda_fp16.h>
#include <cstdint>

// ---------------------------------------------------------------------------
// out = sigmoid(BN( A @ M )),  A (65536 x 512) fp16 built from x, M (512x768)
// pre-combined.  GEMM: fp16 mma.sync m16n8k16, CTA 128x128, 8 warps, KB=64,
// 3-stage cp.async pipeline, XOR-swizzled smem, BN partials fused in epilogue.
// R12: weight-prep GEMM split-K x4 (96 -> 384 CTAs; was ~50us FFMA-bound on
// 96/148 SMs) + tiny deterministic reduce that emits fp16-transposed g_Bf.
// ---------------------------------------------------------------------------

#define NROWS   65536
#define DIN     768
#define KDIM    512
#define EDIM    768

#define KB      64          // K per stage
#define NITER   (KDIM / KB) // 8

// smem stage: Af[128x64] fp16 (16KB) + Bf[128x64] fp16 (16KB), 128B rows,
// 16B-chunk XOR swizzle: off = r*128 + ((c ^ (r&7))<<4)
#define TERMB   16384
#define STG     32768
#define SMEMB   (3 * STG)   // 98304

#define NSPLIT  4           // prep_B split-K factor
#define JCHUNK  (1536 / NSPLIT)

// __device__ scratch (allocation-free rule)
__device__ __align__(16) float   g_Mp[NSPLIT * KDIM * EDIM];   // split-K partials
__device__ __align__(16) __half  g_Bf[EDIM * KDIM];            // [e][k]
__device__ __align__(16) __half  g_Af[(size_t)NROWS * KDIM];   // [n][k]
__device__ __align__(16) __half  g_raw[(size_t)NROWS * EDIM];  // fp16 raw out
__device__ __align__(16) float   g_psum[EDIM * 512];           // [col][rowblk]
__device__ __align__(16) float   g_psqs[EDIM * 512];
__device__ __align__(16) float   g_scale[EDIM];
__device__ __align__(16) float   g_shift[EDIM];

// ---------------- PTX helpers (baseline sm_80+ features only) ---------------
__device__ __forceinline__ uint32_t smem_u32(const void* p) {
    uint32_t a;
    asm("{ .reg .u64 t; cvta.to.shared.u64 t, %1; cvt.u32.u64 %0, t; }" : "=r"(a) : "l"(p));
    return a;
}
__device__ __forceinline__ void cp16(uint32_t dst, const void* src) {
    asm volatile("cp.async.cg.shared.global [%0], [%1], 16;" :: "r"(dst), "l"(src) : "memory");
}
__device__ __forceinline__ void ldsm4(uint32_t* r, uint32_t a) {
    asm volatile("ldmatrix.sync.aligned.m8n8.x4.shared.b16 {%0,%1,%2,%3}, [%4];"
                 : "=r"(r[0]), "=r"(r[1]), "=r"(r[2]), "=r"(r[3]) : "r"(a));
}
__device__ __forceinline__ void mma_f16(float* c, const uint32_t* a,
                                        uint32_t b0, uint32_t b1) {
    asm volatile(
        "mma.sync.aligned.m16n8k16.row.col.f32.f16.f16.f32 "
        "{%0,%1,%2,%3}, {%4,%5,%6,%7}, {%8,%9}, {%0,%1,%2,%3};"
        : "+f"(c[0]), "+f"(c[1]), "+f"(c[2]), "+f"(c[3])
        : "r"(a[0]), "r"(a[1]), "r"(a[2]), "r"(a[3]), "r"(b0), "r"(b1));
}

// ---------------------------------------------------------------------------
// K0a: split-K weight prep.  Partial M = L[:, jr] @ W2[jr, :] per z-slice,
// L(512x1536) computed on the fly.  grid (12, 8, 4), 256 threads, 64x64 tile.
// ---------------------------------------------------------------------------
__global__ void __launch_bounds__(256) prep_B_partial(const float* __restrict__ w1a,
                                                      const float* __restrict__ w2a,
                                                      const float* __restrict__ w1b,
                                                      const float* __restrict__ w2b) {
    __shared__ __align__(16) float As[16][64];
    __shared__ __align__(16) float Bs[16][64];
    const int e0 = blockIdx.x * 64;
    const int i0 = blockIdx.y * 64;
    const int jz = blockIdx.z * JCHUNK;
    const int t  = threadIdx.x;
    const int tx = t & 15;
    const int ty = t >> 4;
    float acc[4][4] = {};

    for (int j0 = jz; j0 < jz + JCHUNK; j0 += 16) {
        {   // A tile: L(i0+r, j0+jq..+3) computed on the fly
            int r  = t >> 2;
            int jq = (t & 3) * 4;
            int i  = i0 + r;
            int j  = j0 + jq;
            float4 v;
            if (j < 768) {
                if (i < 256) {
                    v = *(const float4*)&w2a[(size_t)i * 768 + j];
                } else {
                    float4 a = *(const float4*)&w1a[(size_t)(i - 256) * 768 + j];
                    v = make_float4(0.5f * a.x, 0.5f * a.y, 0.5f * a.z, 0.5f * a.w);
                }
            } else {
                int jj = j - 768;
                if (i < 256) {
                    float4 a = *(const float4*)&w1a[(size_t)i * 768 + jj];
                    v = make_float4(0.5f * a.x, 0.5f * a.y, 0.5f * a.z, 0.5f * a.w);
                } else {
                    float4 a = *(const float4*)&w2a[(size_t)(i - 256) * 768 + jj];
                    float4 b = *(const float4*)&w1a[(size_t)(i - 256) * 768 + jj];
                    v = make_float4(fmaf(0.25f, b.x, 0.5f * a.x),
                                    fmaf(0.25f, b.y, 0.5f * a.y),
                                    fmaf(0.25f, b.z, 0.5f * a.z),
                                    fmaf(0.25f, b.w, 0.5f * a.w));
                }
            }
            As[jq + 0][r] = v.x; As[jq + 1][r] = v.y;
            As[jq + 2][r] = v.z; As[jq + 3][r] = v.w;
        }
        {   // B tile: [w2b ; w1b](j0+k, e0+eq..)
            int k  = t >> 4;
            int eq = (t & 15) * 4;
            int j  = j0 + k;
            const float* src = (j < 768) ? (w2b + (size_t)j * 768)
                                         : (w1b + (size_t)(j - 768) * 768);
            *(float4*)&Bs[k][eq] = *(const float4*)(src + e0 + eq);
        }
        __syncthreads();
        #pragma unroll
        for (int k = 0; k < 16; ++k) {
            float4 a = *(const float4*)&As[k][ty * 4];
            float4 b = *(const float4*)&Bs[k][tx * 4];
            float av[4] = {a.x, a.y, a.z, a.w};
            float bv[4] = {b.x, b.y, b.z, b.w};
            #pragma unroll
            for (int i = 0; i < 4; ++i)
                #pragma unroll
                for (int j = 0; j < 4; ++j)
                    acc[i][j] = fmaf(av[i], bv[j], acc[i][j]);
        }
        __syncthreads();
    }
    float* dst = g_Mp + (size_t)blockIdx.z * KDIM * EDIM;
    #pragma unroll
    for (int i = 0; i < 4; ++i)
        *(float4*)&dst[(size_t)(i0 + ty * 4 + i) * EDIM + e0 + tx * 4] =
            make_float4(acc[i][0], acc[i][1], acc[i][2], acc[i][3]);
}

// ---------------------------------------------------------------------------
// K0b: reduce split-K partials (fixed order) -> g_Bf = fp16(M^T) ([e][k])
// ---------------------------------------------------------------------------
__global__ void __launch_bounds__(256) prep_B_reduce() {
    int idx = blockIdx.x * 256 + threadIdx.x;        // 512*768
    int k = idx / EDIM;
    int e = idx % EDIM;
    float s = g_Mp[idx];
    #pragma unroll
    for (int z = 1; z < NSPLIT; ++z)
        s += g_Mp[(size_t)z * KDIM * EDIM + idx];
    g_Bf[(size_t)e * KDIM + k] = __float2half_rn(s);
}

// ---------------------------------------------------------------------------
// K1: x -> g_Af (fp16).  A(n,k) = x[n,0,k] (k<256) / x[n,1,..]+x[n,2,..]
// ---------------------------------------------------------------------------
__global__ void __launch_bounds__(256) conv_A(const float* __restrict__ X) {
    int id = blockIdx.x * 256 + threadIdx.x;        // NROWS*64 threads
    int n  = id >> 6;
    int k  = (id & 63) * 8;
    const float* p = X + (size_t)n * DIN + k;
    float4 v0 = *(const float4*)p;
    float4 v1 = *(const float4*)(p + 4);
    if (k >= 256) {
        float4 w0 = *(const float4*)(p + 256);
        float4 w1 = *(const float4*)(p + 260);
        v0.x += w0.x; v0.y += w0.y; v0.z += w0.z; v0.w += w0.w;
        v1.x += w1.x; v1.y += w1.y; v1.z += w1.z; v1.w += w1.w;
    }
    __half2 h0 = __float22half2_rn(make_float2(v0.x, v0.y));
    __half2 h1 = __float22half2_rn(make_float2(v0.z, v0.w));
    __half2 h2 = __float22half2_rn(make_float2(v1.x, v1.y));
    __half2 h3 = __float22half2_rn(make_float2(v1.z, v1.w));
    uint4 o;
    o.x = *(uint32_t*)&h0; o.y = *(uint32_t*)&h1;
    o.z = *(uint32_t*)&h2; o.w = *(uint32_t*)&h3;
    *(uint4*)(g_Af + (size_t)n * KDIM + k) = o;
}

// ---------------------------------------------------------------------------
// K2: main GEMM via fp16 mma.sync + fused BN partials.  grid (6, 512).
// ---------------------------------------------------------------------------
__device__ __forceinline__ void stage_issue(uint32_t st, int t, int n0, int e0, int k0) {
    #pragma unroll
    for (int j = 0; j < 8; ++j) {
        int idx  = t + 256 * j;          // 0..2047
        int part = idx >> 10;            // 0: A, 1: B
        int rr   = (idx >> 3) & 127;
        int c    = idx & 7;
        uint32_t dst = st + (uint32_t)(part * TERMB + rr * 128 + ((c ^ (rr & 7)) << 4));
        const __half* g = part ? g_Bf : g_Af;
        int base = part ? e0 : n0;
        cp16(dst, g + (size_t)(base + rr) * KDIM + k0 + c * 8);
    }
    asm volatile("cp.async.commit_group;" ::: "memory");
}

__global__ void __launch_bounds__(256, 2) gemm_mma() {
    extern __shared__ char smem[];
    const uint32_t sb = smem_u32(smem);
    const int t  = threadIdx.x;
    const int w  = t >> 5;
    const int l  = t & 31;
    const int mw = w & 1;                // M-warp (64 rows each)
    const int nw = w >> 1;               // N-warp (32 cols each)
    const int e0 = blockIdx.x * 128;
    const int n0 = blockIdx.y * 128;

    float acc[4][4][4];
    #pragma unroll
    for (int a = 0; a < 4; ++a)
        #pragma unroll
        for (int b = 0; b < 4; ++b)
            #pragma unroll
            for (int c = 0; c < 4; ++c) acc[a][b][c] = 0.f;

    uint32_t arow[4], amask[4];
    #pragma unroll
    for (int mt = 0; mt < 4; ++mt) {
        int row = mw * 64 + mt * 16 + (l & 15);
        arow[mt]  = (uint32_t)(row * 128);
        amask[mt] = (uint32_t)(row & 7);
    }
    const uint32_t ahi = (uint32_t)(l >> 4);
    uint32_t brow[2], bmask[2];
    #pragma unroll
    for (int p = 0; p < 2; ++p) {
        int row = nw * 32 + p * 16 + ((l >> 4) & 1) * 8 + (l & 7);
        brow[p]  = (uint32_t)(row * 128);
        bmask[p] = (uint32_t)(row & 7);
    }
    const uint32_t bhi = (uint32_t)((l >> 3) & 1);

    stage_issue(sb + 0 * STG, t, n0, e0, 0);
    stage_issue(sb + 1 * STG, t, n0, e0, KB);

    int s = 0;
    #pragma unroll 1
    for (int i = 0; i < NITER; ++i) {
        if (i != NITER - 1) asm volatile("cp.async.wait_group 1;" ::: "memory");
        else                asm volatile("cp.async.wait_group 0;" ::: "memory");
        __syncthreads();

        const uint32_t stA = sb + (uint32_t)s * STG;
        const uint32_t stB = stA + TERMB;
        #pragma unroll
        for (int kk = 0; kk < 4; ++kk) {
            const uint32_t ch_a = (uint32_t)(kk * 2) + ahi;
            const uint32_t ch_b = (uint32_t)(kk * 2) + bhi;
            uint32_t Af[4][4], Bf[2][4];
            #pragma unroll
            for (int mt = 0; mt < 4; ++mt)
                ldsm4(Af[mt], stA + arow[mt] + ((ch_a ^ amask[mt]) << 4));
            #pragma unroll
            for (int p = 0; p < 2; ++p)
                ldsm4(Bf[p], stB + brow[p] + ((ch_b ^ bmask[p]) << 4));
            #pragma unroll
            for (int mt = 0; mt < 4; ++mt)
                #pragma unroll
                for (int nt = 0; nt < 4; ++nt) {
                    int p = nt >> 1, h = (nt & 1) * 2;
                    mma_f16(acc[mt][nt], Af[mt], Bf[p][h], Bf[p][h + 1]);
                }
        }

        if (i + 2 < NITER) {
            int s2 = s + 2; if (s2 >= 3) s2 -= 3;
            stage_issue(sb + (uint32_t)s2 * STG, t, n0, e0, (i + 2) * KB);
        }
        if (++s == 3) s = 0;
    }

    // ---- epilogue: store fp16 raw tile + fused BN partial sums --------------
    const int r0 = n0 + mw * 64;
    const int c0 = e0 + nw * 32;
    const int lr = l >> 2;
    const int lc = (l & 3) * 2;
    float cs[8], cq[8];
    #pragma unroll
    for (int j = 0; j < 8; ++j) { cs[j] = 0.f; cq[j] = 0.f; }

    #pragma unroll
    for (int mt = 0; mt < 4; ++mt)
        #pragma unroll
        for (int nt = 0; nt < 4; ++nt) {
            size_t o = (size_t)(r0 + mt * 16 + lr) * EDIM + c0 + nt * 8 + lc;
            float v0 = acc[mt][nt][0], v1 = acc[mt][nt][1];
            float v2 = acc[mt][nt][2], v3 = acc[mt][nt][3];
            *(__half2*)(g_raw + o)            = __floats2half2_rn(v0, v1);
            *(__half2*)(g_raw + o + 8 * EDIM) = __floats2half2_rn(v2, v3);
            cs[nt * 2 + 0] += v0 + v2;
            cs[nt * 2 + 1] += v1 + v3;
            cq[nt * 2 + 0] = fmaf(v0, v0, fmaf(v2, v2, cq[nt * 2 + 0]));
            cq[nt * 2 + 1] = fmaf(v1, v1, fmaf(v3, v3, cq[nt * 2 + 1]));
        }

    // deterministic in-CTA reduction over the 16 threads sharing each column
    __syncthreads();                                   // smem stages now free
    float* red_s = (float*)smem;                       // [16][128]
    float* red_q = (float*)(smem + 8192);              // [16][128]
    const int tid16 = mw * 8 + lr;                     // 0..15
    #pragma unroll
    for (int nt = 0; nt < 4; ++nt) {
        int colc = nw * 32 + nt * 8 + lc;
        red_s[tid16 * 128 + colc]     = cs[nt * 2 + 0];
        red_s[tid16 * 128 + colc + 1] = cs[nt * 2 + 1];
        red_q[tid16 * 128 + colc]     = cq[nt * 2 + 0];
        red_q[tid16 * 128 + colc + 1] = cq[nt * 2 + 1];
    }
    __syncthreads();
    if (t < 128) {
        float s = 0.f, q = 0.f;
        #pragma unroll
        for (int j = 0; j < 16; ++j) {
            s += red_s[j * 128 + t];
            q += red_q[j * 128 + t];
        }
        g_psum[(size_t)(e0 + t) * 512 + blockIdx.y] = s;
        g_psqs[(size_t)(e0 + t) * 512 + blockIdx.y] = q;
    }
}

// ---------------------------------------------------------------------------
// K3: bn_finalize — one warp per column, coalesced contiguous reads.
// ---------------------------------------------------------------------------
__global__ void __launch_bounds__(256) bn_finalize(const float* __restrict__ gamma,
                                                   const float* __restrict__ beta) {
    const int wid = threadIdx.x >> 5;
    const int l   = threadIdx.x & 31;
    const int c   = blockIdx.x * 8 + wid;          // 0..767
    const float* ps = g_psum + (size_t)c * 512;
    const float* pq = g_psqs + (size_t)c * 512;
    float s = 0.f, q = 0.f;
    #pragma unroll
    for (int j = 0; j < 16; ++j) {
        s += ps[l + 32 * j];
        q += pq[l + 32 * j];
    }
    #pragma unroll
    for (int d = 16; d > 0; d >>= 1) {
        s += __shfl_xor_sync(0xFFFFFFFF, s, d);
        q += __shfl_xor_sync(0xFFFFFFFF, q, d);
    }
    if (l == 0) {
        const float inv_n = 1.f / (float)NROWS;
        float mean = s * inv_n;
        float var  = q * inv_n - mean * mean;
        float rstd = rsqrtf(var + 1e-5f);
        float g = gamma[c] * rstd;
        g_scale[c] = g;
        g_shift[c] = beta[c] - mean * g;
    }
}

// ---------------------------------------------------------------------------
// K4: normalize + sigmoid (reads fp16 raw, writes fp32 out)
// ---------------------------------------------------------------------------
__global__ void __launch_bounds__(192) bn_sigmoid(float* __restrict__ OUT) {
    const int row = blockIdx.x;
    const int t   = threadIdx.x;                       // cols t*4..t*4+3
    uint2 rv = *(const uint2*)(g_raw + (size_t)row * EDIM + t * 4);
    __half2 h0 = *(__half2*)&rv.x;
    __half2 h1 = *(__half2*)&rv.y;
    float2 f0 = __half22float2(h0);
    float2 f1 = __half22float2(h1);
    float4 sc = ((const float4*)g_scale)[t];
    float4 sh = ((const float4*)g_shift)[t];
    float4 v;
    v.x = 1.f / (1.f + expf(-(fmaf(f0.x, sc.x, sh.x))));
    v.y = 1.f / (1.f + expf(-(fmaf(f0.y, sc.y, sh.y))));
    v.z = 1.f / (1.f + expf(-(fmaf(f1.x, sc.z, sh.z))));
    v.w = 1.f / (1.f + expf(-(fmaf(f1.y, sc.w, sh.w))));
    ((float4*)(OUT + (size_t)row * EDIM))[t] = v;
}

// ---------------------------------------------------------------------------
extern "C" void kernel_launch(void* const* d_in, const int* in_sizes, int n_in,
                              void* d_out, int out_size) {
    const float* x     = (const float*)d_in[0];
    const float* w1a   = (const float*)d_in[1];
    const float* w2a   = (const float*)d_in[2];
    const float* w1b   = (const float*)d_in[3];
    const float* w2b   = (const float*)d_in[4];
    const float* gamma = (const float*)d_in[5];
    const float* beta  = (const float*)d_in[6];
    float* out = (float*)d_out;

    cudaFuncSetAttribute(gemm_mma, cudaFuncAttributeMaxDynamicSharedMemorySize, SMEMB);

    prep_B_partial<<<dim3(EDIM / 64, 512 / 64, NSPLIT), 256>>>(w1a, w2a, w1b, w2b);
    prep_B_reduce<<<(KDIM * EDIM) / 256, 256>>>();
    conv_A<<<NROWS / 4, 256>>>(x);
    gemm_mma<<<dim3(EDIM / 128, NROWS / 128), 256, SMEMB>>>();
    bn_finalize<<<96, 256>>>(gamma, beta);
    bn_sigmoid<<<NROWS, 192>>>(out);
}

// round 13
// speedup vs baseline: 4.6159x; 1.0427x over previous
#include <cuda_runtime.h>
#include <cuda_bf16.h>
#include <cuda_fp16.h>
#include <cstdint>

// ---------------------------------------------------------------------------
// out = sigmoid(BN( A @ M )),  A (65536 x 512) fp16 built from x, M (512x768)
// pre-combined.  GEMM: fp16 mma.sync m16n8k16, CTA 128x128, 8 warps, KB=64,
// 3-stage cp.async pipeline (fully unrolled, early issue), XOR-swizzled smem,
// BN partials fused in epilogue.  R13: bn_sigmoid re-gridded (grid-stride,
// 1024x256, smem-cached scale/shift); gemm main loop unrolled w/ early issue.
// ---------------------------------------------------------------------------

#define NROWS   65536
#define DIN     768
#define KDIM    512
#define EDIM    768

#define KB      64          // K per stage
#define NITER   (KDIM / KB) // 8

#define TERMB   16384
#define STG     32768
#define SMEMB   (3 * STG)   // 98304

#define NSPLIT  4           // prep_B split-K factor
#define JCHUNK  (1536 / NSPLIT)

// __device__ scratch (allocation-free rule)
__device__ __align__(16) float   g_Mp[NSPLIT * KDIM * EDIM];   // split-K partials
__device__ __align__(16) __half  g_Bf[EDIM * KDIM];            // [e][k]
__device__ __align__(16) __half  g_Af[(size_t)NROWS * KDIM];   // [n][k]
__device__ __align__(16) __half  g_raw[(size_t)NROWS * EDIM];  // fp16 raw out
__device__ __align__(16) float   g_psum[EDIM * 512];           // [col][rowblk]
__device__ __align__(16) float   g_psqs[EDIM * 512];
__device__ __align__(16) float   g_scale[EDIM];
__device__ __align__(16) float   g_shift[EDIM];

// ---------------- PTX helpers (baseline sm_80+ features only) ---------------
__device__ __forceinline__ uint32_t smem_u32(const void* p) {
    uint32_t a;
    asm("{ .reg .u64 t; cvta.to.shared.u64 t, %1; cvt.u32.u64 %0, t; }" : "=r"(a) : "l"(p));
    return a;
}
__device__ __forceinline__ void cp16(uint32_t dst, const void* src) {
    asm volatile("cp.async.cg.shared.global [%0], [%1], 16;" :: "r"(dst), "l"(src) : "memory");
}
__device__ __forceinline__ void ldsm4(uint32_t* r, uint32_t a) {
    asm volatile("ldmatrix.sync.aligned.m8n8.x4.shared.b16 {%0,%1,%2,%3}, [%4];"
                 : "=r"(r[0]), "=r"(r[1]), "=r"(r[2]), "=r"(r[3]) : "r"(a));
}
__device__ __forceinline__ void mma_f16(float* c, const uint32_t* a,
                                        uint32_t b0, uint32_t b1) {
    asm volatile(
        "mma.sync.aligned.m16n8k16.row.col.f32.f16.f16.f32 "
        "{%0,%1,%2,%3}, {%4,%5,%6,%7}, {%8,%9}, {%0,%1,%2,%3};"
        : "+f"(c[0]), "+f"(c[1]), "+f"(c[2]), "+f"(c[3])
        : "r"(a[0]), "r"(a[1]), "r"(a[2]), "r"(a[3]), "r"(b0), "r"(b1));
}

// ---------------------------------------------------------------------------
// K0a: split-K weight prep.   [proven]
// ---------------------------------------------------------------------------
__global__ void __launch_bounds__(256) prep_B_partial(const float* __restrict__ w1a,
                                                      const float* __restrict__ w2a,
                                                      const float* __restrict__ w1b,
                                                      const float* __restrict__ w2b) {
    __shared__ __align__(16) float As[16][64];
    __shared__ __align__(16) float Bs[16][64];
    const int e0 = blockIdx.x * 64;
    const int i0 = blockIdx.y * 64;
    const int jz = blockIdx.z * JCHUNK;
    const int t  = threadIdx.x;
    const int tx = t & 15;
    const int ty = t >> 4;
    float acc[4][4] = {};

    for (int j0 = jz; j0 < jz + JCHUNK; j0 += 16) {
        {
            int r  = t >> 2;
            int jq = (t & 3) * 4;
            int i  = i0 + r;
            int j  = j0 + jq;
            float4 v;
            if (j < 768) {
                if (i < 256) {
                    v = *(const float4*)&w2a[(size_t)i * 768 + j];
                } else {
                    float4 a = *(const float4*)&w1a[(size_t)(i - 256) * 768 + j];
                    v = make_float4(0.5f * a.x, 0.5f * a.y, 0.5f * a.z, 0.5f * a.w);
                }
            } else {
                int jj = j - 768;
                if (i < 256) {
                    float4 a = *(const float4*)&w1a[(size_t)i * 768 + jj];
                    v = make_float4(0.5f * a.x, 0.5f * a.y, 0.5f * a.z, 0.5f * a.w);
                } else {
                    float4 a = *(const float4*)&w2a[(size_t)(i - 256) * 768 + jj];
                    float4 b = *(const float4*)&w1a[(size_t)(i - 256) * 768 + jj];
                    v = make_float4(fmaf(0.25f, b.x, 0.5f * a.x),
                                    fmaf(0.25f, b.y, 0.5f * a.y),
                                    fmaf(0.25f, b.z, 0.5f * a.z),
                                    fmaf(0.25f, b.w, 0.5f * a.w));
                }
            }
            As[jq + 0][r] = v.x; As[jq + 1][r] = v.y;
            As[jq + 2][r] = v.z; As[jq + 3][r] = v.w;
        }
        {
            int k  = t >> 4;
            int eq = (t & 15) * 4;
            int j  = j0 + k;
            const float* src = (j < 768) ? (w2b + (size_t)j * 768)
                                         : (w1b + (size_t)(j - 768) * 768);
            *(float4*)&Bs[k][eq] = *(const float4*)(src + e0 + eq);
        }
        __syncthreads();
        #pragma unroll
        for (int k = 0; k < 16; ++k) {
            float4 a = *(const float4*)&As[k][ty * 4];
            float4 b = *(const float4*)&Bs[k][tx * 4];
            float av[4] = {a.x, a.y, a.z, a.w};
            float bv[4] = {b.x, b.y, b.z, b.w};
            #pragma unroll
            for (int i = 0; i < 4; ++i)
                #pragma unroll
                for (int j = 0; j < 4; ++j)
                    acc[i][j] = fmaf(av[i], bv[j], acc[i][j]);
        }
        __syncthreads();
    }
    float* dst = g_Mp + (size_t)blockIdx.z * KDIM * EDIM;
    #pragma unroll
    for (int i = 0; i < 4; ++i)
        *(float4*)&dst[(size_t)(i0 + ty * 4 + i) * EDIM + e0 + tx * 4] =
            make_float4(acc[i][0], acc[i][1], acc[i][2], acc[i][3]);
}

// ---------------------------------------------------------------------------
// K0b: reduce split-K partials -> g_Bf = fp16(M^T)   [proven]
// ---------------------------------------------------------------------------
__global__ void __launch_bounds__(256) prep_B_reduce() {
    int idx = blockIdx.x * 256 + threadIdx.x;        // 512*768
    int k = idx / EDIM;
    int e = idx % EDIM;
    float s = g_Mp[idx];
    #pragma unroll
    for (int z = 1; z < NSPLIT; ++z)
        s += g_Mp[(size_t)z * KDIM * EDIM + idx];
    g_Bf[(size_t)e * KDIM + k] = __float2half_rn(s);
}

// ---------------------------------------------------------------------------
// K1: x -> g_Af (fp16)   [proven, at DRAM floor]
// ---------------------------------------------------------------------------
__global__ void __launch_bounds__(256) conv_A(const float* __restrict__ X) {
    int id = blockIdx.x * 256 + threadIdx.x;        // NROWS*64 threads
    int n  = id >> 6;
    int k  = (id & 63) * 8;
    const float* p = X + (size_t)n * DIN + k;
    float4 v0 = *(const float4*)p;
    float4 v1 = *(const float4*)(p + 4);
    if (k >= 256) {
        float4 w0 = *(const float4*)(p + 256);
        float4 w1 = *(const float4*)(p + 260);
        v0.x += w0.x; v0.y += w0.y; v0.z += w0.z; v0.w += w0.w;
        v1.x += w1.x; v1.y += w1.y; v1.z += w1.z; v1.w += w1.w;
    }
    __half2 h0 = __float22half2_rn(make_float2(v0.x, v0.y));
    __half2 h1 = __float22half2_rn(make_float2(v0.z, v0.w));
    __half2 h2 = __float22half2_rn(make_float2(v1.x, v1.y));
    __half2 h3 = __float22half2_rn(make_float2(v1.z, v1.w));
    uint4 o;
    o.x = *(uint32_t*)&h0; o.y = *(uint32_t*)&h1;
    o.z = *(uint32_t*)&h2; o.w = *(uint32_t*)&h3;
    *(uint4*)(g_Af + (size_t)n * KDIM + k) = o;
}

// ---------------------------------------------------------------------------
// K2: main GEMM via fp16 mma.sync + fused BN partials.  grid (6, 512).
// Fully unrolled 8-iter pipeline; cp.async for iter i+2 issued right after
// the iteration barrier so loads overlap the whole MMA burst.
// ---------------------------------------------------------------------------
__device__ __forceinline__ void stage_issue(uint32_t st, int t, int n0, int e0, int k0) {
    #pragma unroll
    for (int j = 0; j < 8; ++j) {
        int idx  = t + 256 * j;          // 0..2047
        int part = idx >> 10;            // 0: A, 1: B
        int rr   = (idx >> 3) & 127;
        int c    = idx & 7;
        uint32_t dst = st + (uint32_t)(part * TERMB + rr * 128 + ((c ^ (rr & 7)) << 4));
        const __half* g = part ? g_Bf : g_Af;
        int base = part ? e0 : n0;
        cp16(dst, g + (size_t)(base + rr) * KDIM + k0 + c * 8);
    }
    asm volatile("cp.async.commit_group;" ::: "memory");
}

__global__ void __launch_bounds__(256, 2) gemm_mma() {
    extern __shared__ char smem[];
    const uint32_t sb = smem_u32(smem);
    const int t  = threadIdx.x;
    const int w  = t >> 5;
    const int l  = t & 31;
    const int mw = w & 1;                // M-warp (64 rows each)
    const int nw = w >> 1;               // N-warp (32 cols each)
    const int e0 = blockIdx.x * 128;
    const int n0 = blockIdx.y * 128;

    float acc[4][4][4];
    #pragma unroll
    for (int a = 0; a < 4; ++a)
        #pragma unroll
        for (int b = 0; b < 4; ++b)
            #pragma unroll
            for (int c = 0; c < 4; ++c) acc[a][b][c] = 0.f;

    uint32_t arow[4], amask[4];
    #pragma unroll
    for (int mt = 0; mt < 4; ++mt) {
        int row = mw * 64 + mt * 16 + (l & 15);
        arow[mt]  = (uint32_t)(row * 128);
        amask[mt] = (uint32_t)(row & 7);
    }
    const uint32_t ahi = (uint32_t)(l >> 4);
    uint32_t brow[2], bmask[2];
    #pragma unroll
    for (int p = 0; p < 2; ++p) {
        int row = nw * 32 + p * 16 + ((l >> 4) & 1) * 8 + (l & 7);
        brow[p]  = (uint32_t)(row * 128);
        bmask[p] = (uint32_t)(row & 7);
    }
    const uint32_t bhi = (uint32_t)((l >> 3) & 1);

    stage_issue(sb + 0 * STG, t, n0, e0, 0);
    stage_issue(sb + 1 * STG, t, n0, e0, KB);

    #pragma unroll
    for (int i = 0; i < NITER; ++i) {
        if (i != NITER - 1) asm volatile("cp.async.wait_group 1;" ::: "memory");
        else                asm volatile("cp.async.wait_group 0;" ::: "memory");
        __syncthreads();

        // early issue: buffer (i+2)%3 was consumed in iter i-1; the barrier
        // above makes the overwrite safe, and the loads overlap this iter's mma
        if (i + 2 < NITER)
            stage_issue(sb + (uint32_t)((i + 2) % 3) * STG, t, n0, e0, (i + 2) * KB);

        const uint32_t stA = sb + (uint32_t)(i % 3) * STG;
        const uint32_t stB = stA + TERMB;
        #pragma unroll
        for (int kk = 0; kk < 4; ++kk) {
            const uint32_t ch_a = (uint32_t)(kk * 2) + ahi;
            const uint32_t ch_b = (uint32_t)(kk * 2) + bhi;
            uint32_t Af[4][4], Bf[2][4];
            #pragma unroll
            for (int mt = 0; mt < 4; ++mt)
                ldsm4(Af[mt], stA + arow[mt] + ((ch_a ^ amask[mt]) << 4));
            #pragma unroll
            for (int p = 0; p < 2; ++p)
                ldsm4(Bf[p], stB + brow[p] + ((ch_b ^ bmask[p]) << 4));
            #pragma unroll
            for (int mt = 0; mt < 4; ++mt)
                #pragma unroll
                for (int nt = 0; nt < 4; ++nt) {
                    int p = nt >> 1, h = (nt & 1) * 2;
                    mma_f16(acc[mt][nt], Af[mt], Bf[p][h], Bf[p][h + 1]);
                }
        }
    }

    // ---- epilogue: store fp16 raw tile + fused BN partial sums --------------
    const int r0 = n0 + mw * 64;
    const int c0 = e0 + nw * 32;
    const int lr = l >> 2;
    const int lc = (l & 3) * 2;
    float cs[8], cq[8];
    #pragma unroll
    for (int j = 0; j < 8; ++j) { cs[j] = 0.f; cq[j] = 0.f; }

    #pragma unroll
    for (int mt = 0; mt < 4; ++mt)
        #pragma unroll
        for (int nt = 0; nt < 4; ++nt) {
            size_t o = (size_t)(r0 + mt * 16 + lr) * EDIM + c0 + nt * 8 + lc;
            float v0 = acc[mt][nt][0], v1 = acc[mt][nt][1];
            float v2 = acc[mt][nt][2], v3 = acc[mt][nt][3];
            *(__half2*)(g_raw + o)            = __floats2half2_rn(v0, v1);
            *(__half2*)(g_raw + o + 8 * EDIM) = __floats2half2_rn(v2, v3);
            cs[nt * 2 + 0] += v0 + v2;
            cs[nt * 2 + 1] += v1 + v3;
            cq[nt * 2 + 0] = fmaf(v0, v0, fmaf(v2, v2, cq[nt * 2 + 0]));
            cq[nt * 2 + 1] = fmaf(v1, v1, fmaf(v3, v3, cq[nt * 2 + 1]));
        }

    __syncthreads();                                   // smem stages now free
    float* red_s = (float*)smem;                       // [16][128]
    float* red_q = (float*)(smem + 8192);              // [16][128]
    const int tid16 = mw * 8 + lr;                     // 0..15
    #pragma unroll
    for (int nt = 0; nt < 4; ++nt) {
        int colc = nw * 32 + nt * 8 + lc;
        red_s[tid16 * 128 + colc]     = cs[nt * 2 + 0];
        red_s[tid16 * 128 + colc + 1] = cs[nt * 2 + 1];
        red_q[tid16 * 128 + colc]     = cq[nt * 2 + 0];
        red_q[tid16 * 128 + colc + 1] = cq[nt * 2 + 1];
    }
    __syncthreads();
    if (t < 128) {
        float s = 0.f, q = 0.f;
        #pragma unroll
        for (int j = 0; j < 16; ++j) {
            s += red_s[j * 128 + t];
            q += red_q[j * 128 + t];
        }
        g_psum[(size_t)(e0 + t) * 512 + blockIdx.y] = s;
        g_psqs[(size_t)(e0 + t) * 512 + blockIdx.y] = q;
    }
}

// ---------------------------------------------------------------------------
// K3: bn_finalize — one warp per column.   [proven, 5.5us]
// ---------------------------------------------------------------------------
__global__ void __launch_bounds__(256) bn_finalize(const float* __restrict__ gamma,
                                                   const float* __restrict__ beta) {
    const int wid = threadIdx.x >> 5;
    const int l   = threadIdx.x & 31;
    const int c   = blockIdx.x * 8 + wid;          // 0..767
    const float* ps = g_psum + (size_t)c * 512;
    const float* pq = g_psqs + (size_t)c * 512;
    float s = 0.f, q = 0.f;
    #pragma unroll
    for (int j = 0; j < 16; ++j) {
        s += ps[l + 32 * j];
        q += pq[l + 32 * j];
    }
    #pragma unroll
    for (int d = 16; d > 0; d >>= 1) {
        s += __shfl_xor_sync(0xFFFFFFFF, s, d);
        q += __shfl_xor_sync(0xFFFFFFFF, q, d);
    }
    if (l == 0) {
        const float inv_n = 1.f / (float)NROWS;
        float mean = s * inv_n;
        float var  = q * inv_n - mean * mean;
        float rstd = rsqrtf(var + 1e-5f);
        float g = gamma[c] * rstd;
        g_scale[c] = g;
        g_shift[c] = beta[c] - mean * g;
    }
}

// ---------------------------------------------------------------------------
// K4: normalize + sigmoid.  Grid-stride float4; scale/shift cached in smem.
// 1024 blocks x 256 threads (was 65536 x 192 micro-blocks).
// ---------------------------------------------------------------------------
#define SIGBLK   1024
#define SIGTHR   256
#define NCHUNK4  (NROWS * (EDIM / 4))          // 12.58M float4-chunks

__global__ void __launch_bounds__(SIGTHR) bn_sigmoid(float* __restrict__ OUT) {
    __shared__ float s_sc[EDIM];
    __shared__ float s_sh[EDIM];
    for (int j = threadIdx.x; j < EDIM; j += SIGTHR) {
        s_sc[j] = g_scale[j];
        s_sh[j] = g_shift[j];
    }
    __syncthreads();

    int tid = blockIdx.x * SIGTHR + threadIdx.x;
    for (size_t c = tid; c < (size_t)NCHUNK4; c += (size_t)SIGBLK * SIGTHR) {
        int col4 = (int)(c % (EDIM / 4));          // 0..191
        uint2 rv = *(const uint2*)(g_raw + c * 4);
        __half2 h0 = *(__half2*)&rv.x;
        __half2 h1 = *(__half2*)&rv.y;
        float2 f0 = __half22float2(h0);
        float2 f1 = __half22float2(h1);
        float4 sc = ((const float4*)s_sc)[col4];
        float4 sh = ((const float4*)s_sh)[col4];
        float4 v;
        v.x = 1.f / (1.f + expf(-(fmaf(f0.x, sc.x, sh.x))));
        v.y = 1.f / (1.f + expf(-(fmaf(f0.y, sc.y, sh.y))));
        v.z = 1.f / (1.f + expf(-(fmaf(f1.x, sc.z, sh.z))));
        v.w = 1.f / (1.f + expf(-(fmaf(f1.y, sc.w, sh.w))));
        ((float4*)OUT)[c] = v;
    }
}

// ---------------------------------------------------------------------------
extern "C" void kernel_launch(void* const* d_in, const int* in_sizes, int n_in,
                              void* d_out, int out_size) {
    const float* x     = (const float*)d_in[0];
    const float* w1a   = (const float*)d_in[1];
    const float* w2a   = (const float*)d_in[2];
    const float* w1b   = (const float*)d_in[3];
    const float* w2b   = (const float*)d_in[4];
    const float* gamma = (const float*)d_in[5];
    const float* beta  = (const float*)d_in[6];
    float* out = (float*)d_out;

    cudaFuncSetAttribute(gemm_mma, cudaFuncAttributeMaxDynamicSharedMemorySize, SMEMB);

    prep_B_partial<<<dim3(EDIM / 64, 512 / 64, NSPLIT), 256>>>(w1a, w2a, w1b, w2b);
    prep_B_reduce<<<(KDIM * EDIM) / 256, 256>>>();
    conv_A<<<NROWS / 4, 256>>>(x);
    gemm_mma<<<dim3(EDIM / 128, NROWS / 128), 256, SMEMB>>>();
    bn_finalize<<<96, 256>>>(gamma, beta);
    bn_sigmoid<<<SIGBLK, SIGTHR>>>(out);
}